// round 13
// baseline (speedup 1.0000x reference)
#include <cuda_runtime.h>
#include <cuda_bf16.h>
#include <cuda_fp16.h>
#include <cstdint>
#include <cstddef>

// ---------------- problem constants ----------------
#define N_NODES 50000
#define N_EDGES 800000
#define DIM     128
#define NEG_SLOPE 0.2f

// ---- SMEM: A hi/lo (128 rows) + two B hi/lo buffers, 272B padded rows ----
#define ROWB      272
#define T_SZ      (128 * ROWB)          // 34816
#define AH_OFF    0
#define AL_OFF    T_SZ
#define B0_OFF    (2 * T_SZ)
#define B1_OFF    (4 * T_SZ)
#define SMEM_TOTAL (6 * T_SZ)           // 208896

#define SCAN_BLK 1024
#define MAX_SB   64

// ---------------- scratch (device globals; no allocs allowed) ----------------
__device__ __half g_hq [(size_t)N_NODES * DIM];
__device__ __half g_hk [(size_t)N_NODES * DIM];
__device__ float  g_h1 [(size_t)N_NODES * DIM];
__device__ unsigned g_wpack[9 * 16384];
__device__ int g_cnt[N_NODES];
__device__ int g_off[N_NODES + 1];
__device__ int g_cur[N_NODES];
__device__ int g_csrc[N_EDGES];
__device__ int g_bsum[MAX_SB];

__device__ __forceinline__ float leakyf(float x) { return x >= 0.f ? x : NEG_SLOPE * x; }

static __device__ __forceinline__ unsigned pack_bf2(float a, float b) {
    __nv_bfloat162 h = __floats2bfloat162_rn(a, b);
    return *(unsigned*)&h;
}
static __device__ __forceinline__ float bf16r(float x) {
    return __bfloat162float(__float2bfloat16(x));
}
static __device__ __forceinline__ uint32_t smem_u32(const void* p) {
    uint32_t a;
    asm("{ .reg .u64 t; cvta.to.shared.u64 t, %1; cvt.u32.u64 %0, t; }" : "=r"(a) : "l"(p));
    return a;
}
static __device__ __forceinline__ void cp16(uint32_t d, const void* s) {
    asm volatile("cp.async.cg.shared.global [%0], [%1], 16;" :: "r"(d), "l"(s));
}
static __device__ __forceinline__ void cp_commit() {
    asm volatile("cp.async.commit_group;");
}
static __device__ __forceinline__ void cp_wait0() {
    asm volatile("cp.async.wait_group 0;");
}
static __device__ __forceinline__ void cp_wait1() {
    asm volatile("cp.async.wait_group 1;");
}

// ---------------- CSR build ----------------
__global__ void zero_int(int* __restrict__ p, int n) {
    int i = blockIdx.x * blockDim.x + threadIdx.x;
    if (i < n) p[i] = 0;
}
__global__ void cnt_kernel(const int* __restrict__ dst, int E, int* __restrict__ cnt) {
    int i4 = blockIdx.x * blockDim.x + threadIdx.x;
    int base = i4 * 4;
    if (base + 3 < E) {
        int4 d = __ldg((const int4*)(dst + base));
        atomicAdd(&cnt[d.x], 1);
        atomicAdd(&cnt[d.y], 1);
        atomicAdd(&cnt[d.z], 1);
        atomicAdd(&cnt[d.w], 1);
    } else {
        for (int j = base; j < E; j++) atomicAdd(&cnt[__ldg(&dst[j])], 1);
    }
}
__global__ void scan_p1(const int* __restrict__ cnt, int* __restrict__ bsum, int n) {
    __shared__ int wsh[8];
    int tid = threadIdx.x;
    int base = blockIdx.x * SCAN_BLK;
    int s = 0;
#pragma unroll
    for (int j = 0; j < 4; j++) {
        int i = base + j * 256 + tid;
        if (i < n) s += __ldg(&cnt[i]);
    }
#pragma unroll
    for (int d = 16; d > 0; d >>= 1) s += __shfl_down_sync(0xffffffffu, s, d);
    if ((tid & 31) == 0) wsh[tid >> 5] = s;
    __syncthreads();
    if (tid < 8) {
        int v = wsh[tid];
#pragma unroll
        for (int d = 4; d > 0; d >>= 1) v += __shfl_down_sync(0xffu, v, d);
        if (tid == 0) bsum[blockIdx.x] = v;
    }
}
__global__ void scan_p2(int* __restrict__ bsum, int* __restrict__ off, int nb, int n) {
    int lane = threadIdx.x;
    int v0 = (lane < nb)      ? bsum[lane]      : 0;
    int v1 = (32 + lane < nb) ? bsum[32 + lane] : 0;
    int s0 = v0, s1 = v1;
#pragma unroll
    for (int d = 1; d < 32; d <<= 1) {
        int t0 = __shfl_up_sync(0xffffffffu, s0, d);
        int t1 = __shfl_up_sync(0xffffffffu, s1, d);
        if (lane >= d) { s0 += t0; s1 += t1; }
    }
    int tot0 = __shfl_sync(0xffffffffu, s0, 31);
    int tot1 = __shfl_sync(0xffffffffu, s1, 31);
    if (lane < nb)      bsum[lane]      = s0 - v0;
    if (32 + lane < nb) bsum[32 + lane] = tot0 + s1 - v1;
    if (lane == 0) off[n] = tot0 + tot1;
}
__global__ void scan_p3(const int* __restrict__ cnt, const int* __restrict__ bsum,
                        int* __restrict__ off, int* __restrict__ cur, int n) {
    __shared__ int wsh[32];
    int tid = threadIdx.x;
    int lane = tid & 31, w = tid >> 5;
    int i = blockIdx.x * SCAN_BLK + tid;
    int v = (i < n) ? __ldg(&cnt[i]) : 0;
    int s = v;
#pragma unroll
    for (int d = 1; d < 32; d <<= 1) {
        int t = __shfl_up_sync(0xffffffffu, s, d);
        if (lane >= d) s += t;
    }
    if (lane == 31) wsh[w] = s;
    __syncthreads();
    if (w == 0) {
        int x = wsh[lane];
#pragma unroll
        for (int d = 1; d < 32; d <<= 1) {
            int t = __shfl_up_sync(0xffffffffu, x, d);
            if (lane >= d) x += t;
        }
        wsh[lane] = x;
    }
    __syncthreads();
    int excl = s - v + (w ? wsh[w - 1] : 0) + __ldg(&bsum[blockIdx.x]);
    if (i < n) { off[i] = excl; cur[i] = excl; }
}
__global__ void scatter_kernel(const int* __restrict__ src, const int* __restrict__ dst,
                               int E, int* __restrict__ cur, int* __restrict__ csrc) {
    int i4 = blockIdx.x * blockDim.x + threadIdx.x;
    int base = i4 * 4;
    if (base + 3 < E) {
        int4 d = __ldg((const int4*)(dst + base));
        int4 s = __ldg((const int4*)(src + base));
        csrc[atomicAdd(&cur[d.x], 1)] = s.x;
        csrc[atomicAdd(&cur[d.y], 1)] = s.y;
        csrc[atomicAdd(&cur[d.z], 1)] = s.z;
        csrc[atomicAdd(&cur[d.w], 1)] = s.w;
    } else {
        for (int j = base; j < E; j++) {
            int pos = atomicAdd(&cur[__ldg(&dst[j])], 1);
            csrc[pos] = __ldg(&src[j]);
        }
    }
}

// ---------------- pack weights: bf16 hi/lo images, layout [n][k] ----------------
__global__ void pack_w(const float* __restrict__ Wq, const float* __restrict__ Wk,
                       const float* __restrict__ Wr, const float* __restrict__ Wro) {
    int mat = blockIdx.x;  // 0..8
    const float* W;
    switch (mat) {
        case 0: W = Wq;         break;
        case 1: W = Wk;         break;
        case 2: W = Wr;         break;
        case 3: W = Wq + 16384; break;
        case 4: W = Wk + 16384; break;
        case 5: W = Wr + 16384; break;
        default: W = Wro + (mat - 6) * 16384; break;
    }
    unsigned short* hi = (unsigned short*)(g_wpack + (size_t)mat * 16384);
    unsigned short* lo = (unsigned short*)(g_wpack + (size_t)mat * 16384 + 8192);
    int n  = threadIdx.x & 127;
    int kc = threadIdx.x >> 7;
#pragma unroll
    for (int j = 0; j < 16; j++) {
        int k = kc * 16 + j;
        float w = __ldg(&W[k * 128 + n]);
        __nv_bfloat16 h = __float2bfloat16(w);
        float l = w - __bfloat162float(h);
        hi[n * 128 + k] = __bfloat16_as_ushort(h);
        lo[n * 128 + k] = __bfloat16_as_ushort(__float2bfloat16(l));
    }
}

// ---------------- GEMM building blocks (256 threads/CTA, 128-row tiles) ----------------
static __device__ __forceinline__ void conv_A(char* sm, const float* __restrict__ A,
                                              int row0, int N) {
#pragma unroll
    for (int it = 0; it < 16; it++) {
        int idx = it * 256 + threadIdx.x;
        int r  = idx >> 5;
        int c4 = idx & 31;
        int gidx = row0 + r;
        int gc = gidx < N ? gidx : N - 1;
        float4 v = __ldg(((const float4*)(A + (size_t)gc * 128)) + c4);
        float hx = bf16r(v.x), hy = bf16r(v.y), hz = bf16r(v.z), hw = bf16r(v.w);
        *(uint2*)(sm + AH_OFF + r * ROWB + c4 * 8) =
            make_uint2(pack_bf2(v.x, v.y), pack_bf2(v.z, v.w));
        *(uint2*)(sm + AL_OFF + r * ROWB + c4 * 8) =
            make_uint2(pack_bf2(v.x - hx, v.y - hy), pack_bf2(v.z - hz, v.w - hw));
    }
}

// fused aggregation: warp w aggregates dst rows [w*16, w*16+16) of this tile
// directly from fp16 hq/hk tables into the smem A tile (bf16 hi/lo).
static __device__ __forceinline__ void agg_to_smem(char* sm,
        const int* __restrict__ off, const int* __restrict__ csrc,
        const __half* __restrict__ hq, const __half* __restrict__ hk,
        int row0, int N) {
    int w = threadIdx.x >> 5, lane = threadIdx.x & 31;
#pragma unroll 1
    for (int rr = 0; rr < 16; rr++) {
        int r = w * 16 + rr;
        int row = row0 + r;
        float4 acc = make_float4(0.f, 0.f, 0.f, 0.f);
        if (row < N) {
            int b = __ldg(&off[row]);
            int e = __ldg(&off[row + 1]);
            uint2 qraw = __ldg(((const uint2*)hq) + (size_t)row * 32 + lane);
            float2 q01 = __half22float2(*(const __half2*)&qraw.x);
            float2 q23 = __half22float2(*(const __half2*)&qraw.y);
            for (int base = b; base < e; base += 32) {
                int s = (base + lane < e) ? __ldg(&csrc[base + lane]) : 0;
                int m = min(32, e - base);
                for (int j = 0; j < m; j++) {
                    int sj = __shfl_sync(0xffffffffu, s, j);
                    uint2 kraw = __ldg(((const uint2*)hk) + (size_t)sj * 32 + lane);
                    float2 k01 = __half22float2(*(const __half2*)&kraw.x);
                    float2 k23 = __half22float2(*(const __half2*)&kraw.y);
                    acc.x += leakyf(q01.x + k01.x);
                    acc.y += leakyf(q01.y + k01.y);
                    acc.z += leakyf(q23.x + k23.x);
                    acc.w += leakyf(q23.y + k23.y);
                }
            }
            float inv = 1.f / (float)max(e - b, 1);
            acc.x *= inv; acc.y *= inv; acc.z *= inv; acc.w *= inv;
        }
        float hx = bf16r(acc.x), hy = bf16r(acc.y), hz = bf16r(acc.z), hw = bf16r(acc.w);
        *(uint2*)(sm + AH_OFF + r * ROWB + lane * 8) =
            make_uint2(pack_bf2(acc.x, acc.y), pack_bf2(acc.z, acc.w));
        *(uint2*)(sm + AL_OFF + r * ROWB + lane * 8) =
            make_uint2(pack_bf2(acc.x - hx, acc.y - hy), pack_bf2(acc.z - hz, acc.w - hw));
    }
}

static __device__ __forceinline__ void copy_B_async(uint32_t sbase, int bufOff, int widx) {
    const char* src = (const char*)(g_wpack + (size_t)widx * 16384);
    uint32_t dst = sbase + bufOff;
#pragma unroll
    for (int it = 0; it < 8; it++) {
        int i = it * 256 + threadIdx.x;
        int r = i >> 4, c = i & 15;
        cp16(dst + r * ROWB + c * 16,        src + i * 16);
        cp16(dst + T_SZ + r * ROWB + c * 16, src + 32768 + i * 16);
    }
    cp_commit();
}

static __device__ __forceinline__ void mma_bf16(float* c, const uint32_t* a,
                                                uint32_t b0, uint32_t b1) {
    asm volatile("mma.sync.aligned.m16n8k16.row.col.f32.bf16.bf16.f32 "
                 "{%0,%1,%2,%3}, {%4,%5,%6,%7}, {%8,%9}, {%0,%1,%2,%3};"
                 : "+f"(c[0]), "+f"(c[1]), "+f"(c[2]), "+f"(c[3])
                 : "r"(a[0]), "r"(a[1]), "r"(a[2]), "r"(a[3]), "r"(b0), "r"(b1));
}
static __device__ __forceinline__ void ldsm_x4(uint32_t* r, uint32_t addr) {
    asm volatile("ldmatrix.sync.aligned.m8n8.x4.shared.b16 {%0,%1,%2,%3}, [%4];"
                 : "=r"(r[0]), "=r"(r[1]), "=r"(r[2]), "=r"(r[3]) : "r"(addr));
}

// warp tile 32(M) x 64(N); fused 3-term split (AH*BH + AL*BH + AH*BL)
static __device__ __forceinline__ void run_mma3(float acc[2][8][4], uint32_t sbase,
                                                int bufOff, int mbase, int nbase, int lane) {
    uint32_t aoff = (uint32_t)((mbase + (lane & 15)) * ROWB + (lane >> 4) * 16);
    uint32_t brow = (uint32_t)(nbase + (lane & 7) + ((lane >> 4) << 3));
    uint32_t boff = brow * ROWB + ((lane >> 3) & 1) * 16;
    uint32_t AH = sbase + AH_OFF + aoff;
    uint32_t AL = sbase + AL_OFF + aoff;
    uint32_t BH = sbase + bufOff + boff;
    uint32_t BL = BH + T_SZ;
#pragma unroll
    for (int ks = 0; ks < 8; ks++) {
        uint32_t kb = ks * 32;
        uint32_t ah0[4], ah1[4], al0[4], al1[4];
        ldsm_x4(ah0, AH + kb);
        ldsm_x4(ah1, AH + 16 * ROWB + kb);
        ldsm_x4(al0, AL + kb);
        ldsm_x4(al1, AL + 16 * ROWB + kb);
#pragma unroll
        for (int p = 0; p < 4; p++) {
            uint32_t bh[4], bl[4];
            ldsm_x4(bh, BH + p * (16 * ROWB) + kb);
            ldsm_x4(bl, BL + p * (16 * ROWB) + kb);
            int nf0 = 2 * p, nf1 = 2 * p + 1;
            mma_bf16(acc[0][nf0], ah0, bh[0], bh[1]);
            mma_bf16(acc[1][nf0], ah1, bh[0], bh[1]);
            mma_bf16(acc[0][nf1], ah0, bh[2], bh[3]);
            mma_bf16(acc[1][nf1], ah1, bh[2], bh[3]);
            mma_bf16(acc[0][nf0], al0, bh[0], bh[1]);
            mma_bf16(acc[1][nf0], al1, bh[0], bh[1]);
            mma_bf16(acc[0][nf1], al0, bh[2], bh[3]);
            mma_bf16(acc[1][nf1], al1, bh[2], bh[3]);
            mma_bf16(acc[0][nf0], ah0, bl[0], bl[1]);
            mma_bf16(acc[1][nf0], ah1, bl[0], bl[1]);
            mma_bf16(acc[0][nf1], ah0, bl[2], bl[3]);
            mma_bf16(acc[1][nf1], ah1, bl[2], bl[3]);
        }
    }
}

static __device__ __forceinline__ void zero_acc(float acc[2][8][4]) {
#pragma unroll
    for (int mf = 0; mf < 2; mf++)
#pragma unroll
        for (int nf = 0; nf < 8; nf++)
#pragma unroll
            for (int i = 0; i < 4; i++) acc[mf][nf][i] = 0.f;
}

static __device__ __forceinline__ void epi(float acc[2][8][4], float* __restrict__ out,
                                           int row0, int mbase, int nbase, int g, int t,
                                           const float* b0, const float* b1, const float* b2,
                                           int N, int doAdd) {
    float bias[8][2];
#pragma unroll
    for (int nf = 0; nf < 8; nf++) {
#pragma unroll
        for (int i = 0; i < 2; i++) {
            float bb = 0.f;
            int col = nbase + nf * 8 + t * 2 + i;
            if (b0) bb += __ldg(&b0[col]);
            if (b1) bb += __ldg(&b1[col]);
            if (b2) bb += __ldg(&b2[col]);
            bias[nf][i] = bb;
        }
    }
#pragma unroll
    for (int mf = 0; mf < 2; mf++) {
#pragma unroll
        for (int half = 0; half < 2; half++) {
            int row = row0 + mbase + mf * 16 + g + half * 8;
            if (row < N) {
                float* op = out + (size_t)row * 128 + nbase;
#pragma unroll
                for (int nf = 0; nf < 8; nf++) {
                    float x = acc[mf][nf][half * 2 + 0] + bias[nf][0];
                    float y = acc[mf][nf][half * 2 + 1] + bias[nf][1];
                    float2* p = (float2*)(op + nf * 8 + t * 2);
                    if (doAdd) {
                        float2 o = *p;
                        o.x += x; o.y += y;
                        *p = o;
                    } else {
                        *p = make_float2(x, y);
                    }
                }
            }
        }
    }
}

static __device__ __forceinline__ void epi_h16(float acc[2][8][4], __half* __restrict__ out,
                                               int row0, int mbase, int nbase, int g, int t,
                                               const float* b0, int N) {
    float bias[8][2];
#pragma unroll
    for (int nf = 0; nf < 8; nf++) {
#pragma unroll
        for (int i = 0; i < 2; i++)
            bias[nf][i] = __ldg(&b0[nbase + nf * 8 + t * 2 + i]);
    }
#pragma unroll
    for (int mf = 0; mf < 2; mf++) {
#pragma unroll
        for (int half = 0; half < 2; half++) {
            int row = row0 + mbase + mf * 16 + g + half * 8;
            if (row < N) {
                __half* op = out + (size_t)row * 128 + nbase;
#pragma unroll
                for (int nf = 0; nf < 8; nf++) {
                    float x = acc[mf][nf][half * 2 + 0] + bias[nf][0];
                    float y = acc[mf][nf][half * 2 + 1] + bias[nf][1];
                    *(__half2*)(op + nf * 8 + t * 2) = __floats2half2_rn(x, y);
                }
            }
        }
    }
}

// h = leaky(acc + br): store into A smem (hi/lo) and optionally gmem (fp32)
static __device__ __forceinline__ void store_h(float acc[2][8][4], char* sm,
                                               const float* __restrict__ br_,
                                               float* __restrict__ hout,
                                               int row0, int mbase, int nbase,
                                               int g, int t, int N) {
    float bias[8][2];
#pragma unroll
    for (int nf = 0; nf < 8; nf++) {
#pragma unroll
        for (int i = 0; i < 2; i++)
            bias[nf][i] = __ldg(&br_[nbase + nf * 8 + t * 2 + i]);
    }
#pragma unroll
    for (int mf = 0; mf < 2; mf++) {
#pragma unroll
        for (int half = 0; half < 2; half++) {
            int rl = mbase + mf * 16 + g + half * 8;
            int row = row0 + rl;
#pragma unroll
            for (int nf = 0; nf < 8; nf++) {
                float x = leakyf(acc[mf][nf][half * 2 + 0] + bias[nf][0]);
                float y = leakyf(acc[mf][nf][half * 2 + 1] + bias[nf][1]);
                int c = nbase + nf * 8 + t * 2;
                float hx = bf16r(x), hy = bf16r(y);
                *(unsigned*)(sm + AH_OFF + rl * ROWB + c * 2) = pack_bf2(x, y);
                *(unsigned*)(sm + AL_OFF + rl * ROWB + c * 2) = pack_bf2(x - hx, y - hy);
                if (hout && row < N)
                    *(float2*)(hout + (size_t)row * 128 + c) = make_float2(x, y);
            }
        }
    }
}

// ---------------- kernel: hq=A@Wq+bq ; hk=A@Wk+bk ; [out=A@Wro+bro_sum] ----------------
__global__ void __launch_bounds__(256, 1)
gemm_qk3(const float* __restrict__ A, int wq, int wk, int wo,
         const float* __restrict__ bq, const float* __restrict__ bk,
         const float* __restrict__ bro,
         __half* __restrict__ hq, __half* __restrict__ hk, float* __restrict__ out, int N) {
    extern __shared__ char sm[];
    uint32_t sbase = smem_u32(sm);
    int tid = threadIdx.x, w = tid >> 5, lane = tid & 31;
    int g = lane >> 2, t = lane & 3;
    int mbase = (w >> 1) * 32, nbase = (w & 1) * 64;
    int row0 = blockIdx.x * 128;

    copy_B_async(sbase, B0_OFF, wq);
    conv_A(sm, A, row0, N);
    copy_B_async(sbase, B1_OFF, wk);

    cp_wait1();
    __syncthreads();

    float acc[2][8][4];
    zero_acc(acc);
    run_mma3(acc, sbase, B0_OFF, mbase, nbase, lane);
    epi_h16(acc, hq, row0, mbase, nbase, g, t, bq, N);

    cp_wait0();
    __syncthreads();
    if (wo >= 0) copy_B_async(sbase, B0_OFF, wo);

    zero_acc(acc);
    run_mma3(acc, sbase, B1_OFF, mbase, nbase, lane);
    epi_h16(acc, hk, row0, mbase, nbase, g, t, bk, N);

    if (wo >= 0) {
        cp_wait0();
        __syncthreads();
        zero_acc(acc);
        run_mma3(acc, sbase, B0_OFF, mbase, nbase, lane);
        epi(acc, out, row0, mbase, nbase, g, t, bro, bro + 128, bro + 256, N, 0);
    }
}

// ---------------- fused kernel: agg (in-smem) -> h=leaky(agg@Wr+br) [-> hout]; out += h@Wro ----------------
__global__ void __launch_bounds__(256, 1)
gemm_agg_wr_ro(const int* __restrict__ off, const int* __restrict__ csrc,
               const __half* __restrict__ hq, const __half* __restrict__ hk,
               int wr, int wro,
               const float* __restrict__ br_, float* __restrict__ hout,
               float* __restrict__ out, int N) {
    extern __shared__ char sm[];
    uint32_t sbase = smem_u32(sm);
    int tid = threadIdx.x, w = tid >> 5, lane = tid & 31;
    int g = lane >> 2, t = lane & 3;
    int mbase = (w >> 1) * 32, nbase = (w & 1) * 64;
    int row0 = blockIdx.x * 128;

    copy_B_async(sbase, B0_OFF, wr);
    copy_B_async(sbase, B1_OFF, wro);

    // aggregate 128 dst rows directly into the smem A tile (bf16 hi/lo)
    agg_to_smem(sm, off, csrc, hq, hk, row0, N);

    cp_wait1();                          // B0 (Wr) ready
    __syncthreads();

    float acc[2][8][4];
    zero_acc(acc);
    run_mma3(acc, sbase, B0_OFF, mbase, nbase, lane);

    __syncthreads();                     // all warps done reading A
    store_h(acc, sm, br_, hout, row0, mbase, nbase, g, t, N);
    cp_wait0();                          // B1 (Wro) ready
    __syncthreads();                     // h tiles visible

    zero_acc(acc);
    run_mma3(acc, sbase, B1_OFF, mbase, nbase, lane);
    epi(acc, out, row0, mbase, nbase, g, t, nullptr, nullptr, nullptr, N, 1);
}

// ---------------- launch ----------------
extern "C" void kernel_launch(void* const* d_in, const int* in_sizes, int n_in,
                              void* d_out, int out_size) {
    const float* feats = (const float*)d_in[0];
    const float* Wq    = (const float*)d_in[1];
    const float* bq    = (const float*)d_in[2];
    const float* Wk    = (const float*)d_in[3];
    const float* bk    = (const float*)d_in[4];
    const float* Wr    = (const float*)d_in[5];
    const float* br    = (const float*)d_in[6];
    const float* Wro   = (const float*)d_in[7];
    const float* bro   = (const float*)d_in[8];
    const int*   src   = (const int*)d_in[9];
    const int*   dst   = (const int*)d_in[10];

    int N = in_sizes[0] / DIM;   // 50000
    int E = in_sizes[9];         // 800000
    float* out = (float*)d_out;

    __half *hq, *hk;
    float *h1;
    int *cnt, *off, *cur, *csrc, *bsum;
    cudaGetSymbolAddress((void**)&hq,   g_hq);
    cudaGetSymbolAddress((void**)&hk,   g_hk);
    cudaGetSymbolAddress((void**)&h1,   g_h1);
    cudaGetSymbolAddress((void**)&cnt,  g_cnt);
    cudaGetSymbolAddress((void**)&off,  g_off);
    cudaGetSymbolAddress((void**)&cur,  g_cur);
    cudaGetSymbolAddress((void**)&csrc, g_csrc);
    cudaGetSymbolAddress((void**)&bsum, g_bsum);

    cudaFuncSetAttribute(gemm_qk3,       cudaFuncAttributeMaxDynamicSharedMemorySize, SMEM_TOTAL);
    cudaFuncSetAttribute(gemm_agg_wr_ro, cudaFuncAttributeMaxDynamicSharedMemorySize, SMEM_TOTAL);

    int gM = (N + 127) / 128;    // 391
    int nb = (N + SCAN_BLK - 1) / SCAN_BLK;
    int e4 = (E + 3) / 4;

    // fork a second stream for the CSR build (independent of weights/GEMM-L0)
    cudaStream_t s2;
    cudaStreamCreateWithFlags(&s2, cudaStreamNonBlocking);
    cudaEvent_t evF, evJ;
    cudaEventCreateWithFlags(&evF, cudaEventDisableTiming);
    cudaEventCreateWithFlags(&evJ, cudaEventDisableTiming);

    cudaEventRecord(evF, 0);
    cudaStreamWaitEvent(s2, evF, 0);

    // ---- branch A (s2): CSR build ----
    zero_int<<<(N + 255) / 256, 256, 0, s2>>>(cnt, N);
    cnt_kernel<<<(e4 + 255) / 256, 256, 0, s2>>>(dst, E, cnt);
    scan_p1<<<nb, 256, 0, s2>>>(cnt, bsum, N);
    scan_p2<<<1, 32, 0, s2>>>(bsum, off, nb, N);
    scan_p3<<<nb, SCAN_BLK, 0, s2>>>(cnt, bsum, off, cur, N);
    scatter_kernel<<<(e4 + 255) / 256, 256, 0, s2>>>(src, dst, E, cur, csrc);
    cudaEventRecord(evJ, s2);

    // ---- branch B (stream 0): weights + layer-0 Q/K (+readout 0 folded) ----
    pack_w<<<9, 1024>>>(Wq, Wk, Wr, Wro);
    gemm_qk3<<<gM, 256, SMEM_TOTAL>>>(feats, 0, 1, 6, bq, bk, bro, hq, hk, out, N);

    // join: fused agg+Wr GEMM needs the CSR
    cudaStreamWaitEvent(0, evJ, 0);

    // layer 0: agg + h1 = leaky(agg@Wr+br) + out += h1@Wro1
    gemm_agg_wr_ro<<<gM, 256, SMEM_TOTAL>>>(off, csrc, hq, hk, 2, 7, br, h1, out, N);

    // layer 1
    gemm_qk3<<<gM, 256, SMEM_TOTAL>>>(h1, 3, 4, -1, bq + 128, bk + 128, nullptr,
                                      hq, hk, nullptr, N);
    gemm_agg_wr_ro<<<gM, 256, SMEM_TOTAL>>>(off, csrc, hq, hk, 5, 8, br + 128, nullptr, out, N);

    // NOTE: s2/events intentionally not destroyed (participated in capture;
    // host-side objects only, no device memory).
}

// round 14
// speedup vs baseline: 1.6865x; 1.6865x over previous
#include <cuda_runtime.h>
#include <cuda_bf16.h>
#include <cuda_fp16.h>
#include <cstdint>
#include <cstddef>

// ---------------- problem constants ----------------
#define N_NODES 50000
#define N_EDGES 800000
#define DIM     128
#define NEG_SLOPE 0.2f

// ---- SMEM: A hi/lo (128 rows) + two B hi/lo buffers, 272B padded rows ----
#define ROWB      272
#define T_SZ      (128 * ROWB)          // 34816
#define AH_OFF    0
#define AL_OFF    T_SZ
#define B0_OFF    (2 * T_SZ)
#define B1_OFF    (4 * T_SZ)
#define SMEM_TOTAL (6 * T_SZ)           // 208896

#define SCAN_BLK 1024
#define MAX_SB   64

// ---------------- scratch (device globals; no allocs allowed) ----------------
__device__ __half g_hq [(size_t)N_NODES * DIM];
__device__ __half g_hk [(size_t)N_NODES * DIM];
__device__ float  g_agg[(size_t)N_NODES * DIM];
__device__ float  g_h1 [(size_t)N_NODES * DIM];
__device__ unsigned g_wpack[9 * 16384];
__device__ int g_cnt[N_NODES];
__device__ int g_off[N_NODES + 1];
__device__ int g_cur[N_NODES];
__device__ int g_csrc[N_EDGES];
__device__ int g_bsum[MAX_SB];

__device__ __forceinline__ float leakyf(float x) { return x >= 0.f ? x : NEG_SLOPE * x; }

static __device__ __forceinline__ unsigned pack_bf2(float a, float b) {
    __nv_bfloat162 h = __floats2bfloat162_rn(a, b);
    return *(unsigned*)&h;
}
static __device__ __forceinline__ float bf16r(float x) {
    return __bfloat162float(__float2bfloat16(x));
}
static __device__ __forceinline__ uint32_t smem_u32(const void* p) {
    uint32_t a;
    asm("{ .reg .u64 t; cvta.to.shared.u64 t, %1; cvt.u32.u64 %0, t; }" : "=r"(a) : "l"(p));
    return a;
}
static __device__ __forceinline__ void cp16(uint32_t d, const void* s) {
    asm volatile("cp.async.cg.shared.global [%0], [%1], 16;" :: "r"(d), "l"(s));
}
static __device__ __forceinline__ void cp_commit() {
    asm volatile("cp.async.commit_group;");
}
static __device__ __forceinline__ void cp_wait0() {
    asm volatile("cp.async.wait_group 0;");
}
static __device__ __forceinline__ void cp_wait1() {
    asm volatile("cp.async.wait_group 1;");
}

// ---------------- CSR build ----------------
__global__ void zero_int(int* __restrict__ p, int n) {
    int i = blockIdx.x * blockDim.x + threadIdx.x;
    if (i < n) p[i] = 0;
}
__global__ void cnt_kernel(const int* __restrict__ dst, int E, int* __restrict__ cnt) {
    int i4 = blockIdx.x * blockDim.x + threadIdx.x;
    int base = i4 * 4;
    if (base + 3 < E) {
        int4 d = __ldg((const int4*)(dst + base));
        atomicAdd(&cnt[d.x], 1);
        atomicAdd(&cnt[d.y], 1);
        atomicAdd(&cnt[d.z], 1);
        atomicAdd(&cnt[d.w], 1);
    } else {
        for (int j = base; j < E; j++) atomicAdd(&cnt[__ldg(&dst[j])], 1);
    }
}
__global__ void scan_p1(const int* __restrict__ cnt, int* __restrict__ bsum, int n) {
    __shared__ int wsh[8];
    int tid = threadIdx.x;
    int base = blockIdx.x * SCAN_BLK;
    int s = 0;
#pragma unroll
    for (int j = 0; j < 4; j++) {
        int i = base + j * 256 + tid;
        if (i < n) s += __ldg(&cnt[i]);
    }
#pragma unroll
    for (int d = 16; d > 0; d >>= 1) s += __shfl_down_sync(0xffffffffu, s, d);
    if ((tid & 31) == 0) wsh[tid >> 5] = s;
    __syncthreads();
    if (tid < 8) {
        int v = wsh[tid];
#pragma unroll
        for (int d = 4; d > 0; d >>= 1) v += __shfl_down_sync(0xffu, v, d);
        if (tid == 0) bsum[blockIdx.x] = v;
    }
}
__global__ void scan_p2(int* __restrict__ bsum, int* __restrict__ off, int nb, int n) {
    int lane = threadIdx.x;
    int v0 = (lane < nb)      ? bsum[lane]      : 0;
    int v1 = (32 + lane < nb) ? bsum[32 + lane] : 0;
    int s0 = v0, s1 = v1;
#pragma unroll
    for (int d = 1; d < 32; d <<= 1) {
        int t0 = __shfl_up_sync(0xffffffffu, s0, d);
        int t1 = __shfl_up_sync(0xffffffffu, s1, d);
        if (lane >= d) { s0 += t0; s1 += t1; }
    }
    int tot0 = __shfl_sync(0xffffffffu, s0, 31);
    int tot1 = __shfl_sync(0xffffffffu, s1, 31);
    if (lane < nb)      bsum[lane]      = s0 - v0;
    if (32 + lane < nb) bsum[32 + lane] = tot0 + s1 - v1;
    if (lane == 0) off[n] = tot0 + tot1;
}
__global__ void scan_p3(const int* __restrict__ cnt, const int* __restrict__ bsum,
                        int* __restrict__ off, int* __restrict__ cur, int n) {
    __shared__ int wsh[32];
    int tid = threadIdx.x;
    int lane = tid & 31, w = tid >> 5;
    int i = blockIdx.x * SCAN_BLK + tid;
    int v = (i < n) ? __ldg(&cnt[i]) : 0;
    int s = v;
#pragma unroll
    for (int d = 1; d < 32; d <<= 1) {
        int t = __shfl_up_sync(0xffffffffu, s, d);
        if (lane >= d) s += t;
    }
    if (lane == 31) wsh[w] = s;
    __syncthreads();
    if (w == 0) {
        int x = wsh[lane];
#pragma unroll
        for (int d = 1; d < 32; d <<= 1) {
            int t = __shfl_up_sync(0xffffffffu, x, d);
            if (lane >= d) x += t;
        }
        wsh[lane] = x;
    }
    __syncthreads();
    int excl = s - v + (w ? wsh[w - 1] : 0) + __ldg(&bsum[blockIdx.x]);
    if (i < n) { off[i] = excl; cur[i] = excl; }
}
__global__ void scatter_kernel(const int* __restrict__ src, const int* __restrict__ dst,
                               int E, int* __restrict__ cur, int* __restrict__ csrc) {
    int i4 = blockIdx.x * blockDim.x + threadIdx.x;
    int base = i4 * 4;
    if (base + 3 < E) {
        int4 d = __ldg((const int4*)(dst + base));
        int4 s = __ldg((const int4*)(src + base));
        csrc[atomicAdd(&cur[d.x], 1)] = s.x;
        csrc[atomicAdd(&cur[d.y], 1)] = s.y;
        csrc[atomicAdd(&cur[d.z], 1)] = s.z;
        csrc[atomicAdd(&cur[d.w], 1)] = s.w;
    } else {
        for (int j = base; j < E; j++) {
            int pos = atomicAdd(&cur[__ldg(&dst[j])], 1);
            csrc[pos] = __ldg(&src[j]);
        }
    }
}

// ---------------- CSR aggregation: warp per dst node, fp16 tables ----------------
__global__ void agg_csr(const int* __restrict__ off, const int* __restrict__ csrc,
                        const __half* __restrict__ hq, const __half* __restrict__ hk,
                        float* __restrict__ agg, int N) {
    int warp = (blockIdx.x * blockDim.x + threadIdx.x) >> 5;
    int lane = threadIdx.x & 31;
    if (warp >= N) return;
    int b = __ldg(&off[warp]);
    int e = __ldg(&off[warp + 1]);
    uint2 qraw = __ldg(((const uint2*)hq) + (size_t)warp * 32 + lane);
    float2 q01 = __half22float2(*(const __half2*)&qraw.x);
    float2 q23 = __half22float2(*(const __half2*)&qraw.y);
    float4 q = make_float4(q01.x, q01.y, q23.x, q23.y);
    float4 acc = make_float4(0.f, 0.f, 0.f, 0.f);
    for (int base = b; base < e; base += 32) {
        int s = (base + lane < e) ? __ldg(&csrc[base + lane]) : 0;
        int m = min(32, e - base);
        int j = 0;
        // 2-wide ILP: two independent gathers in flight
        for (; j + 2 <= m; j += 2) {
            int sj0 = __shfl_sync(0xffffffffu, s, j);
            int sj1 = __shfl_sync(0xffffffffu, s, j + 1);
            uint2 k0 = __ldg(((const uint2*)hk) + (size_t)sj0 * 32 + lane);
            uint2 k1 = __ldg(((const uint2*)hk) + (size_t)sj1 * 32 + lane);
            float2 a01 = __half22float2(*(const __half2*)&k0.x);
            float2 a23 = __half22float2(*(const __half2*)&k0.y);
            float2 b01 = __half22float2(*(const __half2*)&k1.x);
            float2 b23 = __half22float2(*(const __half2*)&k1.y);
            acc.x += leakyf(q.x + a01.x) + leakyf(q.x + b01.x);
            acc.y += leakyf(q.y + a01.y) + leakyf(q.y + b01.y);
            acc.z += leakyf(q.z + a23.x) + leakyf(q.z + b23.x);
            acc.w += leakyf(q.w + a23.y) + leakyf(q.w + b23.y);
        }
        for (; j < m; j++) {
            int sj = __shfl_sync(0xffffffffu, s, j);
            uint2 kraw = __ldg(((const uint2*)hk) + (size_t)sj * 32 + lane);
            float2 k01 = __half22float2(*(const __half2*)&kraw.x);
            float2 k23 = __half22float2(*(const __half2*)&kraw.y);
            acc.x += leakyf(q.x + k01.x);
            acc.y += leakyf(q.y + k01.y);
            acc.z += leakyf(q.z + k23.x);
            acc.w += leakyf(q.w + k23.y);
        }
    }
    float inv = 1.f / (float)max(e - b, 1);
    ((float4*)agg)[(size_t)warp * 32 + lane] =
        make_float4(acc.x * inv, acc.y * inv, acc.z * inv, acc.w * inv);
}

// ---------------- pack weights: bf16 hi/lo images, layout [n][k] ----------------
__global__ void pack_w(const float* __restrict__ Wq, const float* __restrict__ Wk,
                       const float* __restrict__ Wr, const float* __restrict__ Wro) {
    int mat = blockIdx.x;  // 0..8
    const float* W;
    switch (mat) {
        case 0: W = Wq;         break;
        case 1: W = Wk;         break;
        case 2: W = Wr;         break;
        case 3: W = Wq + 16384; break;
        case 4: W = Wk + 16384; break;
        case 5: W = Wr + 16384; break;
        default: W = Wro + (mat - 6) * 16384; break;
    }
    unsigned short* hi = (unsigned short*)(g_wpack + (size_t)mat * 16384);
    unsigned short* lo = (unsigned short*)(g_wpack + (size_t)mat * 16384 + 8192);
    int n  = threadIdx.x & 127;
    int kc = threadIdx.x >> 7;
#pragma unroll
    for (int j = 0; j < 16; j++) {
        int k = kc * 16 + j;
        float w = __ldg(&W[k * 128 + n]);
        __nv_bfloat16 h = __float2bfloat16(w);
        float l = w - __bfloat162float(h);
        hi[n * 128 + k] = __bfloat16_as_ushort(h);
        lo[n * 128 + k] = __bfloat16_as_ushort(__float2bfloat16(l));
    }
}

// ---------------- GEMM building blocks (256 threads/CTA, 128-row tiles) ----------------
static __device__ __forceinline__ void conv_A(char* sm, const float* __restrict__ A,
                                              int row0, int N) {
#pragma unroll
    for (int it = 0; it < 16; it++) {
        int idx = it * 256 + threadIdx.x;
        int r  = idx >> 5;
        int c4 = idx & 31;
        int gidx = row0 + r;
        int gc = gidx < N ? gidx : N - 1;
        float4 v = __ldg(((const float4*)(A + (size_t)gc * 128)) + c4);
        float hx = bf16r(v.x), hy = bf16r(v.y), hz = bf16r(v.z), hw = bf16r(v.w);
        *(uint2*)(sm + AH_OFF + r * ROWB + c4 * 8) =
            make_uint2(pack_bf2(v.x, v.y), pack_bf2(v.z, v.w));
        *(uint2*)(sm + AL_OFF + r * ROWB + c4 * 8) =
            make_uint2(pack_bf2(v.x - hx, v.y - hy), pack_bf2(v.z - hz, v.w - hw));
    }
}

static __device__ __forceinline__ void copy_B_async(uint32_t sbase, int bufOff, int widx) {
    const char* src = (const char*)(g_wpack + (size_t)widx * 16384);
    uint32_t dst = sbase + bufOff;
#pragma unroll
    for (int it = 0; it < 8; it++) {
        int i = it * 256 + threadIdx.x;
        int r = i >> 4, c = i & 15;
        cp16(dst + r * ROWB + c * 16,        src + i * 16);
        cp16(dst + T_SZ + r * ROWB + c * 16, src + 32768 + i * 16);
    }
    cp_commit();
}

static __device__ __forceinline__ void mma_bf16(float* c, const uint32_t* a,
                                                uint32_t b0, uint32_t b1) {
    asm volatile("mma.sync.aligned.m16n8k16.row.col.f32.bf16.bf16.f32 "
                 "{%0,%1,%2,%3}, {%4,%5,%6,%7}, {%8,%9}, {%0,%1,%2,%3};"
                 : "+f"(c[0]), "+f"(c[1]), "+f"(c[2]), "+f"(c[3])
                 : "r"(a[0]), "r"(a[1]), "r"(a[2]), "r"(a[3]), "r"(b0), "r"(b1));
}
static __device__ __forceinline__ void ldsm_x4(uint32_t* r, uint32_t addr) {
    asm volatile("ldmatrix.sync.aligned.m8n8.x4.shared.b16 {%0,%1,%2,%3}, [%4];"
                 : "=r"(r[0]), "=r"(r[1]), "=r"(r[2]), "=r"(r[3]) : "r"(addr));
}

// warp tile 32(M) x 64(N); fused 3-term split (AH*BH + AL*BH + AH*BL)
static __device__ __forceinline__ void run_mma3(float acc[2][8][4], uint32_t sbase,
                                                int bufOff, int mbase, int nbase, int lane) {
    uint32_t aoff = (uint32_t)((mbase + (lane & 15)) * ROWB + (lane >> 4) * 16);
    uint32_t brow = (uint32_t)(nbase + (lane & 7) + ((lane >> 4) << 3));
    uint32_t boff = brow * ROWB + ((lane >> 3) & 1) * 16;
    uint32_t AH = sbase + AH_OFF + aoff;
    uint32_t AL = sbase + AL_OFF + aoff;
    uint32_t BH = sbase + bufOff + boff;
    uint32_t BL = BH + T_SZ;
#pragma unroll
    for (int ks = 0; ks < 8; ks++) {
        uint32_t kb = ks * 32;
        uint32_t ah0[4], ah1[4], al0[4], al1[4];
        ldsm_x4(ah0, AH + kb);
        ldsm_x4(ah1, AH + 16 * ROWB + kb);
        ldsm_x4(al0, AL + kb);
        ldsm_x4(al1, AL + 16 * ROWB + kb);
#pragma unroll
        for (int p = 0; p < 4; p++) {
            uint32_t bh[4], bl[4];
            ldsm_x4(bh, BH + p * (16 * ROWB) + kb);
            ldsm_x4(bl, BL + p * (16 * ROWB) + kb);
            int nf0 = 2 * p, nf1 = 2 * p + 1;
            mma_bf16(acc[0][nf0], ah0, bh[0], bh[1]);
            mma_bf16(acc[1][nf0], ah1, bh[0], bh[1]);
            mma_bf16(acc[0][nf1], ah0, bh[2], bh[3]);
            mma_bf16(acc[1][nf1], ah1, bh[2], bh[3]);
            mma_bf16(acc[0][nf0], al0, bh[0], bh[1]);
            mma_bf16(acc[1][nf0], al1, bh[0], bh[1]);
            mma_bf16(acc[0][nf1], al0, bh[2], bh[3]);
            mma_bf16(acc[1][nf1], al1, bh[2], bh[3]);
            mma_bf16(acc[0][nf0], ah0, bl[0], bl[1]);
            mma_bf16(acc[1][nf0], ah1, bl[0], bl[1]);
            mma_bf16(acc[0][nf1], ah0, bl[2], bl[3]);
            mma_bf16(acc[1][nf1], ah1, bl[2], bl[3]);
        }
    }
}

static __device__ __forceinline__ void zero_acc(float acc[2][8][4]) {
#pragma unroll
    for (int mf = 0; mf < 2; mf++)
#pragma unroll
        for (int nf = 0; nf < 8; nf++)
#pragma unroll
            for (int i = 0; i < 4; i++) acc[mf][nf][i] = 0.f;
}

static __device__ __forceinline__ void epi(float acc[2][8][4], float* __restrict__ out,
                                           int row0, int mbase, int nbase, int g, int t,
                                           const float* b0, const float* b1, const float* b2,
                                           int N, int doAdd) {
    float bias[8][2];
#pragma unroll
    for (int nf = 0; nf < 8; nf++) {
#pragma unroll
        for (int i = 0; i < 2; i++) {
            float bb = 0.f;
            int col = nbase + nf * 8 + t * 2 + i;
            if (b0) bb += __ldg(&b0[col]);
            if (b1) bb += __ldg(&b1[col]);
            if (b2) bb += __ldg(&b2[col]);
            bias[nf][i] = bb;
        }
    }
#pragma unroll
    for (int mf = 0; mf < 2; mf++) {
#pragma unroll
        for (int half = 0; half < 2; half++) {
            int row = row0 + mbase + mf * 16 + g + half * 8;
            if (row < N) {
                float* op = out + (size_t)row * 128 + nbase;
#pragma unroll
                for (int nf = 0; nf < 8; nf++) {
                    float x = acc[mf][nf][half * 2 + 0] + bias[nf][0];
                    float y = acc[mf][nf][half * 2 + 1] + bias[nf][1];
                    float2* p = (float2*)(op + nf * 8 + t * 2);
                    if (doAdd) {
                        float2 o = *p;
                        o.x += x; o.y += y;
                        *p = o;
                    } else {
                        *p = make_float2(x, y);
                    }
                }
            }
        }
    }
}

static __device__ __forceinline__ void epi_h16(float acc[2][8][4], __half* __restrict__ out,
                                               int row0, int mbase, int nbase, int g, int t,
                                               const float* b0, int N) {
    float bias[8][2];
#pragma unroll
    for (int nf = 0; nf < 8; nf++) {
#pragma unroll
        for (int i = 0; i < 2; i++)
            bias[nf][i] = __ldg(&b0[nbase + nf * 8 + t * 2 + i]);
    }
#pragma unroll
    for (int mf = 0; mf < 2; mf++) {
#pragma unroll
        for (int half = 0; half < 2; half++) {
            int row = row0 + mbase + mf * 16 + g + half * 8;
            if (row < N) {
                __half* op = out + (size_t)row * 128 + nbase;
#pragma unroll
                for (int nf = 0; nf < 8; nf++) {
                    float x = acc[mf][nf][half * 2 + 0] + bias[nf][0];
                    float y = acc[mf][nf][half * 2 + 1] + bias[nf][1];
                    *(__half2*)(op + nf * 8 + t * 2) = __floats2half2_rn(x, y);
                }
            }
        }
    }
}

// h = leaky(acc + br): store into A smem (hi/lo) and optionally gmem (fp32)
static __device__ __forceinline__ void store_h(float acc[2][8][4], char* sm,
                                               const float* __restrict__ br_,
                                               float* __restrict__ hout,
                                               int row0, int mbase, int nbase,
                                               int g, int t, int N) {
    float bias[8][2];
#pragma unroll
    for (int nf = 0; nf < 8; nf++) {
#pragma unroll
        for (int i = 0; i < 2; i++)
            bias[nf][i] = __ldg(&br_[nbase + nf * 8 + t * 2 + i]);
    }
#pragma unroll
    for (int mf = 0; mf < 2; mf++) {
#pragma unroll
        for (int half = 0; half < 2; half++) {
            int rl = mbase + mf * 16 + g + half * 8;
            int row = row0 + rl;
#pragma unroll
            for (int nf = 0; nf < 8; nf++) {
                float x = leakyf(acc[mf][nf][half * 2 + 0] + bias[nf][0]);
                float y = leakyf(acc[mf][nf][half * 2 + 1] + bias[nf][1]);
                int c = nbase + nf * 8 + t * 2;
                float hx = bf16r(x), hy = bf16r(y);
                *(unsigned*)(sm + AH_OFF + rl * ROWB + c * 2) = pack_bf2(x, y);
                *(unsigned*)(sm + AL_OFF + rl * ROWB + c * 2) = pack_bf2(x - hx, y - hy);
                if (hout && row < N)
                    *(float2*)(hout + (size_t)row * 128 + c) = make_float2(x, y);
            }
        }
    }
}

// ---------------- kernel: hq=A@Wq+bq ; hk=A@Wk+bk ; [out=A@Wro+bro_sum] ----------------
__global__ void __launch_bounds__(256, 1)
gemm_qk3(const float* __restrict__ A, int wq, int wk, int wo,
         const float* __restrict__ bq, const float* __restrict__ bk,
         const float* __restrict__ bro,
         __half* __restrict__ hq, __half* __restrict__ hk, float* __restrict__ out, int N) {
    extern __shared__ char sm[];
    uint32_t sbase = smem_u32(sm);
    int tid = threadIdx.x, w = tid >> 5, lane = tid & 31;
    int g = lane >> 2, t = lane & 3;
    int mbase = (w >> 1) * 32, nbase = (w & 1) * 64;
    int row0 = blockIdx.x * 128;

    copy_B_async(sbase, B0_OFF, wq);
    conv_A(sm, A, row0, N);
    copy_B_async(sbase, B1_OFF, wk);

    cp_wait1();
    __syncthreads();

    float acc[2][8][4];
    zero_acc(acc);
    run_mma3(acc, sbase, B0_OFF, mbase, nbase, lane);
    epi_h16(acc, hq, row0, mbase, nbase, g, t, bq, N);

    cp_wait0();
    __syncthreads();
    if (wo >= 0) copy_B_async(sbase, B0_OFF, wo);

    zero_acc(acc);
    run_mma3(acc, sbase, B1_OFF, mbase, nbase, lane);
    epi_h16(acc, hk, row0, mbase, nbase, g, t, bk, N);

    if (wo >= 0) {
        cp_wait0();
        __syncthreads();
        zero_acc(acc);
        run_mma3(acc, sbase, B0_OFF, mbase, nbase, lane);
        epi(acc, out, row0, mbase, nbase, g, t, bro, bro + 128, bro + 256, N, 0);
    }
}

// ---------------- kernel: h = leaky(agg@Wr+br) [-> hout fp32]; out += h@Wro ----------------
__global__ void __launch_bounds__(256, 1)
gemm_wr_ro(const float* __restrict__ agg, int wr, int wro,
           const float* __restrict__ br_, float* __restrict__ hout,
           float* __restrict__ out, int N) {
    extern __shared__ char sm[];
    uint32_t sbase = smem_u32(sm);
    int tid = threadIdx.x, w = tid >> 5, lane = tid & 31;
    int g = lane >> 2, t = lane & 3;
    int mbase = (w >> 1) * 32, nbase = (w & 1) * 64;
    int row0 = blockIdx.x * 128;

    copy_B_async(sbase, B0_OFF, wr);
    conv_A(sm, agg, row0, N);
    copy_B_async(sbase, B1_OFF, wro);

    cp_wait1();
    __syncthreads();

    float acc[2][8][4];
    zero_acc(acc);
    run_mma3(acc, sbase, B0_OFF, mbase, nbase, lane);

    __syncthreads();
    store_h(acc, sm, br_, hout, row0, mbase, nbase, g, t, N);
    cp_wait0();
    __syncthreads();

    zero_acc(acc);
    run_mma3(acc, sbase, B1_OFF, mbase, nbase, lane);
    epi(acc, out, row0, mbase, nbase, g, t, nullptr, nullptr, nullptr, N, 1);
}

// ---------------- launch ----------------
extern "C" void kernel_launch(void* const* d_in, const int* in_sizes, int n_in,
                              void* d_out, int out_size) {
    const float* feats = (const float*)d_in[0];
    const float* Wq    = (const float*)d_in[1];
    const float* bq    = (const float*)d_in[2];
    const float* Wk    = (const float*)d_in[3];
    const float* bk    = (const float*)d_in[4];
    const float* Wr    = (const float*)d_in[5];
    const float* br    = (const float*)d_in[6];
    const float* Wro   = (const float*)d_in[7];
    const float* bro   = (const float*)d_in[8];
    const int*   src   = (const int*)d_in[9];
    const int*   dst   = (const int*)d_in[10];

    int N = in_sizes[0] / DIM;   // 50000
    int E = in_sizes[9];         // 800000
    float* out = (float*)d_out;

    __half *hq, *hk;
    float *agg, *h1;
    int *cnt, *off, *cur, *csrc, *bsum;
    cudaGetSymbolAddress((void**)&hq,   g_hq);
    cudaGetSymbolAddress((void**)&hk,   g_hk);
    cudaGetSymbolAddress((void**)&agg,  g_agg);
    cudaGetSymbolAddress((void**)&h1,   g_h1);
    cudaGetSymbolAddress((void**)&cnt,  g_cnt);
    cudaGetSymbolAddress((void**)&off,  g_off);
    cudaGetSymbolAddress((void**)&cur,  g_cur);
    cudaGetSymbolAddress((void**)&csrc, g_csrc);
    cudaGetSymbolAddress((void**)&bsum, g_bsum);

    cudaFuncSetAttribute(gemm_qk3,   cudaFuncAttributeMaxDynamicSharedMemorySize, SMEM_TOTAL);
    cudaFuncSetAttribute(gemm_wr_ro, cudaFuncAttributeMaxDynamicSharedMemorySize, SMEM_TOTAL);

    int gM = (N + 127) / 128;    // 391
    int gAgg = (N * 32 + 255) / 256;
    int nb = (N + SCAN_BLK - 1) / SCAN_BLK;
    int e4 = (E + 3) / 4;

    // fork a second stream for the CSR build (independent of weights/GEMM-L0)
    cudaStream_t s2;
    cudaStreamCreateWithFlags(&s2, cudaStreamNonBlocking);
    cudaEvent_t evF, evJ;
    cudaEventCreateWithFlags(&evF, cudaEventDisableTiming);
    cudaEventCreateWithFlags(&evJ, cudaEventDisableTiming);

    cudaEventRecord(evF, 0);
    cudaStreamWaitEvent(s2, evF, 0);

    // ---- branch A (s2): CSR build ----
    zero_int<<<(N + 255) / 256, 256, 0, s2>>>(cnt, N);
    cnt_kernel<<<(e4 + 255) / 256, 256, 0, s2>>>(dst, E, cnt);
    scan_p1<<<nb, 256, 0, s2>>>(cnt, bsum, N);
    scan_p2<<<1, 32, 0, s2>>>(bsum, off, nb, N);
    scan_p3<<<nb, SCAN_BLK, 0, s2>>>(cnt, bsum, off, cur, N);
    scatter_kernel<<<(e4 + 255) / 256, 256, 0, s2>>>(src, dst, E, cur, csrc);
    cudaEventRecord(evJ, s2);

    // ---- branch B (stream 0): weights + layer-0 Q/K (+readout 0 folded) ----
    pack_w<<<9, 1024>>>(Wq, Wk, Wr, Wro);
    gemm_qk3<<<gM, 256, SMEM_TOTAL>>>(feats, 0, 1, 6, bq, bk, bro, hq, hk, out, N);

    // join: agg needs both branches
    cudaStreamWaitEvent(0, evJ, 0);

    agg_csr<<<gAgg, 256>>>(off, csrc, hq, hk, agg, N);
    gemm_wr_ro<<<gM, 256, SMEM_TOTAL>>>(agg, 2, 7, br, h1, out, N);

    gemm_qk3<<<gM, 256, SMEM_TOTAL>>>(h1, 3, 4, -1, bq + 128, bk + 128, nullptr,
                                      hq, hk, nullptr, N);
    agg_csr<<<gAgg, 256>>>(off, csrc, hq, hk, agg, N);
    gemm_wr_ro<<<gM, 256, SMEM_TOTAL>>>(agg, 5, 8, br + 128, nullptr, out, N);

    // NOTE: s2/events intentionally not destroyed (participated in capture;
    // host-side objects only, no device memory).
}

// round 15
// speedup vs baseline: 2.5086x; 1.4875x over previous
#include <cuda_runtime.h>
#include <cuda_fp16.h>
#include <cstdint>
#include <cstddef>

// ---------------- problem constants ----------------
#define N_NODES 50000
#define N_EDGES 800000
#define DIM     128
#define NEG_SLOPE 0.2f

// ---- SMEM: A (128 rows fp16) + two B buffers, 272B padded rows ----
#define ROWB      272
#define T_SZ      (128 * ROWB)          // 34816
#define A_OFF     0
#define B0_OFF    T_SZ
#define B1_OFF    (2 * T_SZ)
#define SMEM_TOTAL (3 * T_SZ)           // 104448

#define SCAN_BLK 1024
#define MAX_SB   64

// ---------------- scratch (device globals; no allocs allowed) ----------------
__device__ __half g_hq [(size_t)N_NODES * DIM];
__device__ __half g_hk [(size_t)N_NODES * DIM];
__device__ float  g_agg[(size_t)N_NODES * DIM];
__device__ float  g_h1 [(size_t)N_NODES * DIM];
__device__ unsigned g_wpack[9 * 8192];      // 9 x fp16 [n][k] images (32 KB each)
__device__ int g_cnt[N_NODES];
__device__ int g_off[N_NODES + 1];
__device__ int g_cur[N_NODES];
__device__ int g_csrc[N_EDGES];
__device__ int g_bsum[MAX_SB];

__device__ __forceinline__ float leakyf(float x) { return x >= 0.f ? x : NEG_SLOPE * x; }

static __device__ __forceinline__ unsigned pack_h2(float a, float b) {
    __half2 h = __floats2half2_rn(a, b);
    return *(unsigned*)&h;
}
static __device__ __forceinline__ uint32_t smem_u32(const void* p) {
    uint32_t a;
    asm("{ .reg .u64 t; cvta.to.shared.u64 t, %1; cvt.u32.u64 %0, t; }" : "=r"(a) : "l"(p));
    return a;
}
static __device__ __forceinline__ void cp16(uint32_t d, const void* s) {
    asm volatile("cp.async.cg.shared.global [%0], [%1], 16;" :: "r"(d), "l"(s));
}
static __device__ __forceinline__ void cp_commit() {
    asm volatile("cp.async.commit_group;");
}
static __device__ __forceinline__ void cp_wait0() {
    asm volatile("cp.async.wait_group 0;");
}
static __device__ __forceinline__ void cp_wait1() {
    asm volatile("cp.async.wait_group 1;");
}

// ---------------- CSR build ----------------
__global__ void zero_int(int* __restrict__ p, int n) {
    int i = blockIdx.x * blockDim.x + threadIdx.x;
    if (i < n) p[i] = 0;
}
__global__ void cnt_kernel(const int* __restrict__ dst, int E, int* __restrict__ cnt) {
    int i4 = blockIdx.x * blockDim.x + threadIdx.x;
    int base = i4 * 4;
    if (base + 3 < E) {
        int4 d = __ldg((const int4*)(dst + base));
        atomicAdd(&cnt[d.x], 1);
        atomicAdd(&cnt[d.y], 1);
        atomicAdd(&cnt[d.z], 1);
        atomicAdd(&cnt[d.w], 1);
    } else {
        for (int j = base; j < E; j++) atomicAdd(&cnt[__ldg(&dst[j])], 1);
    }
}
__global__ void scan_p1(const int* __restrict__ cnt, int* __restrict__ bsum, int n) {
    __shared__ int wsh[8];
    int tid = threadIdx.x;
    int base = blockIdx.x * SCAN_BLK;
    int s = 0;
#pragma unroll
    for (int j = 0; j < 4; j++) {
        int i = base + j * 256 + tid;
        if (i < n) s += __ldg(&cnt[i]);
    }
#pragma unroll
    for (int d = 16; d > 0; d >>= 1) s += __shfl_down_sync(0xffffffffu, s, d);
    if ((tid & 31) == 0) wsh[tid >> 5] = s;
    __syncthreads();
    if (tid < 8) {
        int v = wsh[tid];
#pragma unroll
        for (int d = 4; d > 0; d >>= 1) v += __shfl_down_sync(0xffu, v, d);
        if (tid == 0) bsum[blockIdx.x] = v;
    }
}
__global__ void scan_p2(int* __restrict__ bsum, int* __restrict__ off, int nb, int n) {
    int lane = threadIdx.x;
    int v0 = (lane < nb)      ? bsum[lane]      : 0;
    int v1 = (32 + lane < nb) ? bsum[32 + lane] : 0;
    int s0 = v0, s1 = v1;
#pragma unroll
    for (int d = 1; d < 32; d <<= 1) {
        int t0 = __shfl_up_sync(0xffffffffu, s0, d);
        int t1 = __shfl_up_sync(0xffffffffu, s1, d);
        if (lane >= d) { s0 += t0; s1 += t1; }
    }
    int tot0 = __shfl_sync(0xffffffffu, s0, 31);
    int tot1 = __shfl_sync(0xffffffffu, s1, 31);
    if (lane < nb)      bsum[lane]      = s0 - v0;
    if (32 + lane < nb) bsum[32 + lane] = tot0 + s1 - v1;
    if (lane == 0) off[n] = tot0 + tot1;
}
__global__ void scan_p3(const int* __restrict__ cnt, const int* __restrict__ bsum,
                        int* __restrict__ off, int* __restrict__ cur, int n) {
    __shared__ int wsh[32];
    int tid = threadIdx.x;
    int lane = tid & 31, w = tid >> 5;
    int i = blockIdx.x * SCAN_BLK + tid;
    int v = (i < n) ? __ldg(&cnt[i]) : 0;
    int s = v;
#pragma unroll
    for (int d = 1; d < 32; d <<= 1) {
        int t = __shfl_up_sync(0xffffffffu, s, d);
        if (lane >= d) s += t;
    }
    if (lane == 31) wsh[w] = s;
    __syncthreads();
    if (w == 0) {
        int x = wsh[lane];
#pragma unroll
        for (int d = 1; d < 32; d <<= 1) {
            int t = __shfl_up_sync(0xffffffffu, x, d);
            if (lane >= d) x += t;
        }
        wsh[lane] = x;
    }
    __syncthreads();
    int excl = s - v + (w ? wsh[w - 1] : 0) + __ldg(&bsum[blockIdx.x]);
    if (i < n) { off[i] = excl; cur[i] = excl; }
}
__global__ void scatter_kernel(const int* __restrict__ src, const int* __restrict__ dst,
                               int E, int* __restrict__ cur, int* __restrict__ csrc) {
    int i4 = blockIdx.x * blockDim.x + threadIdx.x;
    int base = i4 * 4;
    if (base + 3 < E) {
        int4 d = __ldg((const int4*)(dst + base));
        int4 s = __ldg((const int4*)(src + base));
        csrc[atomicAdd(&cur[d.x], 1)] = s.x;
        csrc[atomicAdd(&cur[d.y], 1)] = s.y;
        csrc[atomicAdd(&cur[d.z], 1)] = s.z;
        csrc[atomicAdd(&cur[d.w], 1)] = s.w;
    } else {
        for (int j = base; j < E; j++) {
            int pos = atomicAdd(&cur[__ldg(&dst[j])], 1);
            csrc[pos] = __ldg(&src[j]);
        }
    }
}

// ---------------- CSR aggregation: warp per dst node, fp16 tables ----------------
__global__ void agg_csr(const int* __restrict__ off, const int* __restrict__ csrc,
                        const __half* __restrict__ hq, const __half* __restrict__ hk,
                        float* __restrict__ agg, int N) {
    int warp = (blockIdx.x * blockDim.x + threadIdx.x) >> 5;
    int lane = threadIdx.x & 31;
    if (warp >= N) return;
    int b = __ldg(&off[warp]);
    int e = __ldg(&off[warp + 1]);
    uint2 qraw = __ldg(((const uint2*)hq) + (size_t)warp * 32 + lane);
    float2 q01 = __half22float2(*(const __half2*)&qraw.x);
    float2 q23 = __half22float2(*(const __half2*)&qraw.y);
    float4 q = make_float4(q01.x, q01.y, q23.x, q23.y);
    float4 acc = make_float4(0.f, 0.f, 0.f, 0.f);
    for (int base = b; base < e; base += 32) {
        int s = (base + lane < e) ? __ldg(&csrc[base + lane]) : 0;
        int m = min(32, e - base);
        for (int j = 0; j < m; j++) {
            int sj = __shfl_sync(0xffffffffu, s, j);
            uint2 kraw = __ldg(((const uint2*)hk) + (size_t)sj * 32 + lane);
            float2 k01 = __half22float2(*(const __half2*)&kraw.x);
            float2 k23 = __half22float2(*(const __half2*)&kraw.y);
            acc.x += leakyf(q.x + k01.x);
            acc.y += leakyf(q.y + k01.y);
            acc.z += leakyf(q.z + k23.x);
            acc.w += leakyf(q.w + k23.y);
        }
    }
    float inv = 1.f / (float)max(e - b, 1);
    ((float4*)agg)[(size_t)warp * 32 + lane] =
        make_float4(acc.x * inv, acc.y * inv, acc.z * inv, acc.w * inv);
}

// ---------------- pack weights: fp16 images, layout [n][k] ----------------
__global__ void pack_w(const float* __restrict__ Wq, const float* __restrict__ Wk,
                       const float* __restrict__ Wr, const float* __restrict__ Wro) {
    int mat = blockIdx.x;  // 0..8
    const float* W;
    switch (mat) {
        case 0: W = Wq;         break;
        case 1: W = Wk;         break;
        case 2: W = Wr;         break;
        case 3: W = Wq + 16384; break;
        case 4: W = Wk + 16384; break;
        case 5: W = Wr + 16384; break;
        default: W = Wro + (mat - 6) * 16384; break;
    }
    unsigned short* img = (unsigned short*)(g_wpack + (size_t)mat * 8192);
    int n  = threadIdx.x & 127;
    int kc = threadIdx.x >> 7;
#pragma unroll
    for (int j = 0; j < 16; j++) {
        int k = kc * 16 + j;
        float w = __ldg(&W[k * 128 + n]);
        __half h = __float2half_rn(w);
        img[n * 128 + k] = *(unsigned short*)&h;
    }
}

// ---------------- GEMM building blocks (256 threads/CTA, 128-row fp16 tiles) ----------------
static __device__ __forceinline__ void conv_A(char* sm, const float* __restrict__ A,
                                              int row0, int N) {
#pragma unroll
    for (int it = 0; it < 16; it++) {
        int idx = it * 256 + threadIdx.x;   // 0..4095
        int r  = idx >> 5;
        int c4 = idx & 31;
        int gidx = row0 + r;
        int gc = gidx < N ? gidx : N - 1;
        float4 v = __ldg(((const float4*)(A + (size_t)gc * 128)) + c4);
        *(uint2*)(sm + A_OFF + r * ROWB + c4 * 8) =
            make_uint2(pack_h2(v.x, v.y), pack_h2(v.z, v.w));
    }
}

// async copy one fp16 weight image into a B buffer; caller waits on group
static __device__ __forceinline__ void copy_B_async(uint32_t sbase, int bufOff, int widx) {
    const char* src = (const char*)(g_wpack + (size_t)widx * 8192);
    uint32_t dst = sbase + bufOff;
#pragma unroll
    for (int it = 0; it < 8; it++) {
        int i = it * 256 + threadIdx.x;   // 0..2047
        int r = i >> 4, c = i & 15;
        cp16(dst + r * ROWB + c * 16, src + i * 16);
    }
    cp_commit();
}

static __device__ __forceinline__ void mma_f16(float* c, const uint32_t* a,
                                               uint32_t b0, uint32_t b1) {
    asm volatile("mma.sync.aligned.m16n8k16.row.col.f32.f16.f16.f32 "
                 "{%0,%1,%2,%3}, {%4,%5,%6,%7}, {%8,%9}, {%0,%1,%2,%3};"
                 : "+f"(c[0]), "+f"(c[1]), "+f"(c[2]), "+f"(c[3])
                 : "r"(a[0]), "r"(a[1]), "r"(a[2]), "r"(a[3]), "r"(b0), "r"(b1));
}
static __device__ __forceinline__ void ldsm_x4(uint32_t* r, uint32_t addr) {
    asm volatile("ldmatrix.sync.aligned.m8n8.x4.shared.b16 {%0,%1,%2,%3}, [%4];"
                 : "=r"(r[0]), "=r"(r[1]), "=r"(r[2]), "=r"(r[3]) : "r"(addr));
}

// warp tile 32(M) x 64(N), single-term fp16 MMA
static __device__ __forceinline__ void run_mma(float acc[2][8][4], uint32_t sbase,
                                               int bufOff, int mbase, int nbase, int lane) {
    uint32_t aoff = (uint32_t)((mbase + (lane & 15)) * ROWB + (lane >> 4) * 16);
    uint32_t brow = (uint32_t)(nbase + (lane & 7) + ((lane >> 4) << 3));
    uint32_t boff = brow * ROWB + ((lane >> 3) & 1) * 16;
    uint32_t Aa = sbase + A_OFF + aoff;
    uint32_t Ba = sbase + bufOff + boff;
#pragma unroll
    for (int ks = 0; ks < 8; ks++) {
        uint32_t kb = ks * 32;
        uint32_t a0[4], a1[4];
        ldsm_x4(a0, Aa + kb);
        ldsm_x4(a1, Aa + 16 * ROWB + kb);
#pragma unroll
        for (int p = 0; p < 4; p++) {
            uint32_t b[4];
            ldsm_x4(b, Ba + p * (16 * ROWB) + kb);
            int nf0 = 2 * p, nf1 = 2 * p + 1;
            mma_f16(acc[0][nf0], a0, b[0], b[1]);
            mma_f16(acc[1][nf0], a1, b[0], b[1]);
            mma_f16(acc[0][nf1], a0, b[2], b[3]);
            mma_f16(acc[1][nf1], a1, b[2], b[3]);
        }
    }
}

static __device__ __forceinline__ void zero_acc(float acc[2][8][4]) {
#pragma unroll
    for (int mf = 0; mf < 2; mf++)
#pragma unroll
        for (int nf = 0; nf < 8; nf++)
#pragma unroll
            for (int i = 0; i < 4; i++) acc[mf][nf][i] = 0.f;
}

static __device__ __forceinline__ void epi(float acc[2][8][4], float* __restrict__ out,
                                           int row0, int mbase, int nbase, int g, int t,
                                           const float* b0, const float* b1, const float* b2,
                                           int N, int doAdd) {
    float bias[8][2];
#pragma unroll
    for (int nf = 0; nf < 8; nf++) {
#pragma unroll
        for (int i = 0; i < 2; i++) {
            float bb = 0.f;
            int col = nbase + nf * 8 + t * 2 + i;
            if (b0) bb += __ldg(&b0[col]);
            if (b1) bb += __ldg(&b1[col]);
            if (b2) bb += __ldg(&b2[col]);
            bias[nf][i] = bb;
        }
    }
#pragma unroll
    for (int mf = 0; mf < 2; mf++) {
#pragma unroll
        for (int half = 0; half < 2; half++) {
            int row = row0 + mbase + mf * 16 + g + half * 8;
            if (row < N) {
                float* op = out + (size_t)row * 128 + nbase;
#pragma unroll
                for (int nf = 0; nf < 8; nf++) {
                    float x = acc[mf][nf][half * 2 + 0] + bias[nf][0];
                    float y = acc[mf][nf][half * 2 + 1] + bias[nf][1];
                    float2* p = (float2*)(op + nf * 8 + t * 2);
                    if (doAdd) {
                        float2 o = *p;
                        o.x += x; o.y += y;
                        *p = o;
                    } else {
                        *p = make_float2(x, y);
                    }
                }
            }
        }
    }
}

static __device__ __forceinline__ void epi_h16(float acc[2][8][4], __half* __restrict__ out,
                                               int row0, int mbase, int nbase, int g, int t,
                                               const float* b0, int N) {
    float bias[8][2];
#pragma unroll
    for (int nf = 0; nf < 8; nf++) {
#pragma unroll
        for (int i = 0; i < 2; i++)
            bias[nf][i] = __ldg(&b0[nbase + nf * 8 + t * 2 + i]);
    }
#pragma unroll
    for (int mf = 0; mf < 2; mf++) {
#pragma unroll
        for (int half = 0; half < 2; half++) {
            int row = row0 + mbase + mf * 16 + g + half * 8;
            if (row < N) {
                __half* op = out + (size_t)row * 128 + nbase;
#pragma unroll
                for (int nf = 0; nf < 8; nf++) {
                    float x = acc[mf][nf][half * 2 + 0] + bias[nf][0];
                    float y = acc[mf][nf][half * 2 + 1] + bias[nf][1];
                    *(__half2*)(op + nf * 8 + t * 2) = __floats2half2_rn(x, y);
                }
            }
        }
    }
}

// h = leaky(acc + br): store fp16 into A smem and fp32 to gmem (if hout)
static __device__ __forceinline__ void store_h(float acc[2][8][4], char* sm,
                                               const float* __restrict__ br_,
                                               float* __restrict__ hout,
                                               int row0, int mbase, int nbase,
                                               int g, int t, int N) {
    float bias[8][2];
#pragma unroll
    for (int nf = 0; nf < 8; nf++) {
#pragma unroll
        for (int i = 0; i < 2; i++)
            bias[nf][i] = __ldg(&br_[nbase + nf * 8 + t * 2 + i]);
    }
#pragma unroll
    for (int mf = 0; mf < 2; mf++) {
#pragma unroll
        for (int half = 0; half < 2; half++) {
            int rl = mbase + mf * 16 + g + half * 8;
            int row = row0 + rl;
#pragma unroll
            for (int nf = 0; nf < 8; nf++) {
                float x = leakyf(acc[mf][nf][half * 2 + 0] + bias[nf][0]);
                float y = leakyf(acc[mf][nf][half * 2 + 1] + bias[nf][1]);
                int c = nbase + nf * 8 + t * 2;
                *(unsigned*)(sm + A_OFF + rl * ROWB + c * 2) = pack_h2(x, y);
                if (hout && row < N)
                    *(float2*)(hout + (size_t)row * 128 + c) = make_float2(x, y);
            }
        }
    }
}

// ---------------- kernel: hq=A@Wq+bq ; hk=A@Wk+bk ; [out=A@Wro+bro_sum] ----------------
__global__ void __launch_bounds__(256, 2)
gemm_qk3(const float* __restrict__ A, int wq, int wk, int wo,
         const float* __restrict__ bq, const float* __restrict__ bk,
         const float* __restrict__ bro,
         __half* __restrict__ hq, __half* __restrict__ hk, float* __restrict__ out, int N) {
    extern __shared__ char sm[];
    uint32_t sbase = smem_u32(sm);
    int tid = threadIdx.x, w = tid >> 5, lane = tid & 31;
    int g = lane >> 2, t = lane & 3;
    int mbase = (w >> 1) * 32, nbase = (w & 1) * 64;
    int row0 = blockIdx.x * 128;

    copy_B_async(sbase, B0_OFF, wq);
    conv_A(sm, A, row0, N);
    copy_B_async(sbase, B1_OFF, wk);

    cp_wait1();
    __syncthreads();

    float acc[2][8][4];
    zero_acc(acc);
    run_mma(acc, sbase, B0_OFF, mbase, nbase, lane);
    epi_h16(acc, hq, row0, mbase, nbase, g, t, bq, N);

    cp_wait0();
    __syncthreads();
    if (wo >= 0) copy_B_async(sbase, B0_OFF, wo);

    zero_acc(acc);
    run_mma(acc, sbase, B1_OFF, mbase, nbase, lane);
    epi_h16(acc, hk, row0, mbase, nbase, g, t, bk, N);

    if (wo >= 0) {
        cp_wait0();
        __syncthreads();
        zero_acc(acc);
        run_mma(acc, sbase, B0_OFF, mbase, nbase, lane);
        epi(acc, out, row0, mbase, nbase, g, t, bro, bro + 128, bro + 256, N, 0);
    }
}

// ---------------- kernel: h = leaky(agg@Wr+br) [-> hout fp32]; out += h@Wro ----------------
__global__ void __launch_bounds__(256, 2)
gemm_wr_ro(const float* __restrict__ agg, int wr, int wro,
           const float* __restrict__ br_, float* __restrict__ hout,
           float* __restrict__ out, int N) {
    extern __shared__ char sm[];
    uint32_t sbase = smem_u32(sm);
    int tid = threadIdx.x, w = tid >> 5, lane = tid & 31;
    int g = lane >> 2, t = lane & 3;
    int mbase = (w >> 1) * 32, nbase = (w & 1) * 64;
    int row0 = blockIdx.x * 128;

    copy_B_async(sbase, B0_OFF, wr);
    conv_A(sm, agg, row0, N);
    copy_B_async(sbase, B1_OFF, wro);

    cp_wait1();
    __syncthreads();

    float acc[2][8][4];
    zero_acc(acc);
    run_mma(acc, sbase, B0_OFF, mbase, nbase, lane);

    __syncthreads();
    store_h(acc, sm, br_, hout, row0, mbase, nbase, g, t, N);
    cp_wait0();
    __syncthreads();

    zero_acc(acc);
    run_mma(acc, sbase, B1_OFF, mbase, nbase, lane);
    epi(acc, out, row0, mbase, nbase, g, t, nullptr, nullptr, nullptr, N, 1);
}

// ---------------- launch ----------------
extern "C" void kernel_launch(void* const* d_in, const int* in_sizes, int n_in,
                              void* d_out, int out_size) {
    const float* feats = (const float*)d_in[0];
    const float* Wq    = (const float*)d_in[1];
    const float* bq    = (const float*)d_in[2];
    const float* Wk    = (const float*)d_in[3];
    const float* bk    = (const float*)d_in[4];
    const float* Wr    = (const float*)d_in[5];
    const float* br    = (const float*)d_in[6];
    const float* Wro   = (const float*)d_in[7];
    const float* bro   = (const float*)d_in[8];
    const int*   src   = (const int*)d_in[9];
    const int*   dst   = (const int*)d_in[10];

    int N = in_sizes[0] / DIM;   // 50000
    int E = in_sizes[9];         // 800000
    float* out = (float*)d_out;

    __half *hq, *hk;
    float *agg, *h1;
    int *cnt, *off, *cur, *csrc, *bsum;
    cudaGetSymbolAddress((void**)&hq,   g_hq);
    cudaGetSymbolAddress((void**)&hk,   g_hk);
    cudaGetSymbolAddress((void**)&agg,  g_agg);
    cudaGetSymbolAddress((void**)&h1,   g_h1);
    cudaGetSymbolAddress((void**)&cnt,  g_cnt);
    cudaGetSymbolAddress((void**)&off,  g_off);
    cudaGetSymbolAddress((void**)&cur,  g_cur);
    cudaGetSymbolAddress((void**)&csrc, g_csrc);
    cudaGetSymbolAddress((void**)&bsum, g_bsum);

    cudaFuncSetAttribute(gemm_qk3,   cudaFuncAttributeMaxDynamicSharedMemorySize, SMEM_TOTAL);
    cudaFuncSetAttribute(gemm_wr_ro, cudaFuncAttributeMaxDynamicSharedMemorySize, SMEM_TOTAL);

    int gM = (N + 127) / 128;    // 391
    int gAgg = (N * 32 + 255) / 256;
    int nb = (N + SCAN_BLK - 1) / SCAN_BLK;
    int e4 = (E + 3) / 4;

    // fork a second stream for the CSR build (independent of weights/GEMM-L0)
    cudaStream_t s2;
    cudaStreamCreateWithFlags(&s2, cudaStreamNonBlocking);
    cudaEvent_t evF, evJ;
    cudaEventCreateWithFlags(&evF, cudaEventDisableTiming);
    cudaEventCreateWithFlags(&evJ, cudaEventDisableTiming);

    cudaEventRecord(evF, 0);
    cudaStreamWaitEvent(s2, evF, 0);

    // ---- branch A (s2): CSR build ----
    zero_int<<<(N + 255) / 256, 256, 0, s2>>>(cnt, N);
    cnt_kernel<<<(e4 + 255) / 256, 256, 0, s2>>>(dst, E, cnt);
    scan_p1<<<nb, 256, 0, s2>>>(cnt, bsum, N);
    scan_p2<<<1, 32, 0, s2>>>(bsum, off, nb, N);
    scan_p3<<<nb, SCAN_BLK, 0, s2>>>(cnt, bsum, off, cur, N);
    scatter_kernel<<<(e4 + 255) / 256, 256, 0, s2>>>(src, dst, E, cur, csrc);
    cudaEventRecord(evJ, s2);

    // ---- branch B (stream 0): weights + layer-0 Q/K (+readout 0 folded) ----
    pack_w<<<9, 1024>>>(Wq, Wk, Wr, Wro);
    gemm_qk3<<<gM, 256, SMEM_TOTAL>>>(feats, 0, 1, 6, bq, bk, bro, hq, hk, out, N);

    // join: agg needs both branches
    cudaStreamWaitEvent(0, evJ, 0);

    agg_csr<<<gAgg, 256>>>(off, csrc, hq, hk, agg, N);
    gemm_wr_ro<<<gM, 256, SMEM_TOTAL>>>(agg, 2, 7, br, h1, out, N);

    gemm_qk3<<<gM, 256, SMEM_TOTAL>>>(h1, 3, 4, -1, bq + 128, bk + 128, nullptr,
                                      hq, hk, nullptr, N);
    agg_csr<<<gAgg, 256>>>(off, csrc, hq, hk, agg, N);
    gemm_wr_ro<<<gM, 256, SMEM_TOTAL>>>(agg, 5, 8, br + 128, nullptr, out, N);

    // NOTE: s2/events intentionally not destroyed (participated in capture;
    // host-side objects only, no device memory).
}

// round 16
// speedup vs baseline: 2.6235x; 1.0458x over previous
#include <cuda_runtime.h>
#include <cuda_fp16.h>
#include <cstdint>
#include <cstddef>

// ---------------- problem constants ----------------
#define N_NODES 50000
#define N_EDGES 800000
#define DIM     128
#define NEG_SLOPE 0.2f

// ---- SMEM: A (128 rows fp16) + two B buffers, 272B padded rows ----
#define ROWB      272
#define T_SZ      (128 * ROWB)          // 34816
#define A_OFF     0
#define B0_OFF    T_SZ
#define B1_OFF    (2 * T_SZ)
#define SMEM_TOTAL (3 * T_SZ)           // 104448

#define SCAN_BLK 1024
#define MAX_SB   64

// ---------------- scratch (device globals; no allocs allowed) ----------------
__device__ __half g_hq [(size_t)N_NODES * DIM];
__device__ __half g_hk [(size_t)N_NODES * DIM];
__device__ __half g_agg[(size_t)N_NODES * DIM];
__device__ __half g_h1 [(size_t)N_NODES * DIM];
__device__ unsigned g_wpack[9 * 8192];      // 9 x fp16 [n][k] images
__device__ int g_cnt[N_NODES];
__device__ int g_off[N_NODES + 1];
__device__ int g_cur[N_NODES];
__device__ int g_csrc[N_EDGES];
__device__ int g_bsum[MAX_SB];

__device__ __forceinline__ float leakyf(float x) { return x >= 0.f ? x : NEG_SLOPE * x; }

static __device__ __forceinline__ unsigned pack_h2(float a, float b) {
    __half2 h = __floats2half2_rn(a, b);
    return *(unsigned*)&h;
}
static __device__ __forceinline__ uint32_t smem_u32(const void* p) {
    uint32_t a;
    asm("{ .reg .u64 t; cvta.to.shared.u64 t, %1; cvt.u32.u64 %0, t; }" : "=r"(a) : "l"(p));
    return a;
}
static __device__ __forceinline__ void cp16(uint32_t d, const void* s) {
    asm volatile("cp.async.cg.shared.global [%0], [%1], 16;" :: "r"(d), "l"(s));
}
static __device__ __forceinline__ void cp_commit() {
    asm volatile("cp.async.commit_group;");
}
static __device__ __forceinline__ void cp_wait0() {
    asm volatile("cp.async.wait_group 0;");
}
static __device__ __forceinline__ void cp_wait1() {
    asm volatile("cp.async.wait_group 1;");
}

// ---------------- CSR build ----------------
__global__ void zero_int(int* __restrict__ p, int n) {
    int i = blockIdx.x * blockDim.x + threadIdx.x;
    if (i < n) p[i] = 0;
}
__global__ void cnt_kernel(const int* __restrict__ dst, int E, int* __restrict__ cnt) {
    int i4 = blockIdx.x * blockDim.x + threadIdx.x;
    int base = i4 * 4;
    if (base + 3 < E) {
        int4 d = __ldg((const int4*)(dst + base));
        atomicAdd(&cnt[d.x], 1);
        atomicAdd(&cnt[d.y], 1);
        atomicAdd(&cnt[d.z], 1);
        atomicAdd(&cnt[d.w], 1);
    } else {
        for (int j = base; j < E; j++) atomicAdd(&cnt[__ldg(&dst[j])], 1);
    }
}
__global__ void scan_p1(const int* __restrict__ cnt, int* __restrict__ bsum, int n) {
    __shared__ int wsh[8];
    int tid = threadIdx.x;
    int base = blockIdx.x * SCAN_BLK;
    int s = 0;
#pragma unroll
    for (int j = 0; j < 4; j++) {
        int i = base + j * 256 + tid;
        if (i < n) s += __ldg(&cnt[i]);
    }
#pragma unroll
    for (int d = 16; d > 0; d >>= 1) s += __shfl_down_sync(0xffffffffu, s, d);
    if ((tid & 31) == 0) wsh[tid >> 5] = s;
    __syncthreads();
    if (tid < 8) {
        int v = wsh[tid];
#pragma unroll
        for (int d = 4; d > 0; d >>= 1) v += __shfl_down_sync(0xffu, v, d);
        if (tid == 0) bsum[blockIdx.x] = v;
    }
}
__global__ void scan_p2(int* __restrict__ bsum, int* __restrict__ off, int nb, int n) {
    int lane = threadIdx.x;
    int v0 = (lane < nb)      ? bsum[lane]      : 0;
    int v1 = (32 + lane < nb) ? bsum[32 + lane] : 0;
    int s0 = v0, s1 = v1;
#pragma unroll
    for (int d = 1; d < 32; d <<= 1) {
        int t0 = __shfl_up_sync(0xffffffffu, s0, d);
        int t1 = __shfl_up_sync(0xffffffffu, s1, d);
        if (lane >= d) { s0 += t0; s1 += t1; }
    }
    int tot0 = __shfl_sync(0xffffffffu, s0, 31);
    int tot1 = __shfl_sync(0xffffffffu, s1, 31);
    if (lane < nb)      bsum[lane]      = s0 - v0;
    if (32 + lane < nb) bsum[32 + lane] = tot0 + s1 - v1;
    if (lane == 0) off[n] = tot0 + tot1;
}
__global__ void scan_p3(const int* __restrict__ cnt, const int* __restrict__ bsum,
                        int* __restrict__ off, int* __restrict__ cur, int n) {
    __shared__ int wsh[32];
    int tid = threadIdx.x;
    int lane = tid & 31, w = tid >> 5;
    int i = blockIdx.x * SCAN_BLK + tid;
    int v = (i < n) ? __ldg(&cnt[i]) : 0;
    int s = v;
#pragma unroll
    for (int d = 1; d < 32; d <<= 1) {
        int t = __shfl_up_sync(0xffffffffu, s, d);
        if (lane >= d) s += t;
    }
    if (lane == 31) wsh[w] = s;
    __syncthreads();
    if (w == 0) {
        int x = wsh[lane];
#pragma unroll
        for (int d = 1; d < 32; d <<= 1) {
            int t = __shfl_up_sync(0xffffffffu, x, d);
            if (lane >= d) x += t;
        }
        wsh[lane] = x;
    }
    __syncthreads();
    int excl = s - v + (w ? wsh[w - 1] : 0) + __ldg(&bsum[blockIdx.x]);
    if (i < n) { off[i] = excl; cur[i] = excl; }
}
__global__ void scatter_kernel(const int* __restrict__ src, const int* __restrict__ dst,
                               int E, int* __restrict__ cur, int* __restrict__ csrc) {
    int i4 = blockIdx.x * blockDim.x + threadIdx.x;
    int base = i4 * 4;
    if (base + 3 < E) {
        int4 d = __ldg((const int4*)(dst + base));
        int4 s = __ldg((const int4*)(src + base));
        csrc[atomicAdd(&cur[d.x], 1)] = s.x;
        csrc[atomicAdd(&cur[d.y], 1)] = s.y;
        csrc[atomicAdd(&cur[d.z], 1)] = s.z;
        csrc[atomicAdd(&cur[d.w], 1)] = s.w;
    } else {
        for (int j = base; j < E; j++) {
            int pos = atomicAdd(&cur[__ldg(&dst[j])], 1);
            csrc[pos] = __ldg(&src[j]);
        }
    }
}

// ---------------- CSR aggregation: warp per dst node, fp16 in/out ----------------
__global__ void agg_csr(const int* __restrict__ off, const int* __restrict__ csrc,
                        const __half* __restrict__ hq, const __half* __restrict__ hk,
                        __half* __restrict__ agg, int N) {
    int warp = (blockIdx.x * blockDim.x + threadIdx.x) >> 5;
    int lane = threadIdx.x & 31;
    if (warp >= N) return;
    int b = __ldg(&off[warp]);
    int e = __ldg(&off[warp + 1]);
    uint2 qraw = __ldg(((const uint2*)hq) + (size_t)warp * 32 + lane);
    float2 q01 = __half22float2(*(const __half2*)&qraw.x);
    float2 q23 = __half22float2(*(const __half2*)&qraw.y);
    float4 q = make_float4(q01.x, q01.y, q23.x, q23.y);
    float4 acc = make_float4(0.f, 0.f, 0.f, 0.f);
    for (int base = b; base < e; base += 32) {
        int s = (base + lane < e) ? __ldg(&csrc[base + lane]) : 0;
        int m = min(32, e - base);
        for (int j = 0; j < m; j++) {
            int sj = __shfl_sync(0xffffffffu, s, j);
            uint2 kraw = __ldg(((const uint2*)hk) + (size_t)sj * 32 + lane);
            float2 k01 = __half22float2(*(const __half2*)&kraw.x);
            float2 k23 = __half22float2(*(const __half2*)&kraw.y);
            acc.x += leakyf(q.x + k01.x);
            acc.y += leakyf(q.y + k01.y);
            acc.z += leakyf(q.z + k23.x);
            acc.w += leakyf(q.w + k23.y);
        }
    }
    float inv = 1.f / (float)max(e - b, 1);
    uint2 o;
    o.x = pack_h2(acc.x * inv, acc.y * inv);
    o.y = pack_h2(acc.z * inv, acc.w * inv);
    ((uint2*)agg)[(size_t)warp * 32 + lane] = o;
}

// ---------------- pack weights: fp16 images, layout [n][k] ----------------
__global__ void pack_w(const float* __restrict__ Wq, const float* __restrict__ Wk,
                       const float* __restrict__ Wr, const float* __restrict__ Wro) {
    int mat = blockIdx.x;  // 0..8
    const float* W;
    switch (mat) {
        case 0: W = Wq;         break;
        case 1: W = Wk;         break;
        case 2: W = Wr;         break;
        case 3: W = Wq + 16384; break;
        case 4: W = Wk + 16384; break;
        case 5: W = Wr + 16384; break;
        default: W = Wro + (mat - 6) * 16384; break;
    }
    unsigned short* img = (unsigned short*)(g_wpack + (size_t)mat * 8192);
    int n  = threadIdx.x & 127;
    int kc = threadIdx.x >> 7;
#pragma unroll
    for (int j = 0; j < 16; j++) {
        int k = kc * 16 + j;
        float w = __ldg(&W[k * 128 + n]);
        __half h = __float2half_rn(w);
        img[n * 128 + k] = *(unsigned short*)&h;
    }
}

// ---------------- GEMM building blocks (256 threads/CTA, 128-row fp16 tiles) ----------------
// fp32 source: load + convert + store
static __device__ __forceinline__ void conv_A(char* sm, const float* __restrict__ A,
                                              int row0, int N) {
#pragma unroll
    for (int it = 0; it < 16; it++) {
        int idx = it * 256 + threadIdx.x;   // 0..4095
        int r  = idx >> 5;
        int c4 = idx & 31;
        int gidx = row0 + r;
        int gc = gidx < N ? gidx : N - 1;
        float4 v = __ldg(((const float4*)(A + (size_t)gc * 128)) + c4);
        *(uint2*)(sm + A_OFF + r * ROWB + c4 * 8) =
            make_uint2(pack_h2(v.x, v.y), pack_h2(v.z, v.w));
    }
}

// fp16 source: pure async tile copy (no conversion pass); no commit
static __device__ __forceinline__ void copy_A16_nc(uint32_t sbase, const __half* __restrict__ A,
                                                   int row0, int N) {
#pragma unroll
    for (int it = 0; it < 8; it++) {
        int i = it * 256 + threadIdx.x;   // 0..2047
        int r = i >> 4, c = i & 15;       // 16B chunks per 256B row
        int gidx = row0 + r;
        int gc = gidx < N ? gidx : N - 1;
        cp16(sbase + A_OFF + r * ROWB + c * 16, A + (size_t)gc * 128 + c * 8);
    }
}

// weight image copy into a B buffer; no commit
static __device__ __forceinline__ void copy_B_nc(uint32_t sbase, int bufOff, int widx) {
    const char* src = (const char*)(g_wpack + (size_t)widx * 8192);
    uint32_t dst = sbase + bufOff;
#pragma unroll
    for (int it = 0; it < 8; it++) {
        int i = it * 256 + threadIdx.x;   // 0..2047
        int r = i >> 4, c = i & 15;
        cp16(dst + r * ROWB + c * 16, src + i * 16);
    }
}

static __device__ __forceinline__ void mma_f16(float* c, const uint32_t* a,
                                               uint32_t b0, uint32_t b1) {
    asm volatile("mma.sync.aligned.m16n8k16.row.col.f32.f16.f16.f32 "
                 "{%0,%1,%2,%3}, {%4,%5,%6,%7}, {%8,%9}, {%0,%1,%2,%3};"
                 : "+f"(c[0]), "+f"(c[1]), "+f"(c[2]), "+f"(c[3])
                 : "r"(a[0]), "r"(a[1]), "r"(a[2]), "r"(a[3]), "r"(b0), "r"(b1));
}
static __device__ __forceinline__ void ldsm_x4(uint32_t* r, uint32_t addr) {
    asm volatile("ldmatrix.sync.aligned.m8n8.x4.shared.b16 {%0,%1,%2,%3}, [%4];"
                 : "=r"(r[0]), "=r"(r[1]), "=r"(r[2]), "=r"(r[3]) : "r"(addr));
}

// warp tile 32(M) x 64(N), single-term fp16 MMA
static __device__ __forceinline__ void run_mma(float acc[2][8][4], uint32_t sbase,
                                               int bufOff, int mbase, int nbase, int lane) {
    uint32_t aoff = (uint32_t)((mbase + (lane & 15)) * ROWB + (lane >> 4) * 16);
    uint32_t brow = (uint32_t)(nbase + (lane & 7) + ((lane >> 4) << 3));
    uint32_t boff = brow * ROWB + ((lane >> 3) & 1) * 16;
    uint32_t Aa = sbase + A_OFF + aoff;
    uint32_t Ba = sbase + bufOff + boff;
#pragma unroll
    for (int ks = 0; ks < 8; ks++) {
        uint32_t kb = ks * 32;
        uint32_t a0[4], a1[4];
        ldsm_x4(a0, Aa + kb);
        ldsm_x4(a1, Aa + 16 * ROWB + kb);
#pragma unroll
        for (int p = 0; p < 4; p++) {
            uint32_t b[4];
            ldsm_x4(b, Ba + p * (16 * ROWB) + kb);
            int nf0 = 2 * p, nf1 = 2 * p + 1;
            mma_f16(acc[0][nf0], a0, b[0], b[1]);
            mma_f16(acc[1][nf0], a1, b[0], b[1]);
            mma_f16(acc[0][nf1], a0, b[2], b[3]);
            mma_f16(acc[1][nf1], a1, b[2], b[3]);
        }
    }
}

static __device__ __forceinline__ void zero_acc(float acc[2][8][4]) {
#pragma unroll
    for (int mf = 0; mf < 2; mf++)
#pragma unroll
        for (int nf = 0; nf < 8; nf++)
#pragma unroll
            for (int i = 0; i < 4; i++) acc[mf][nf][i] = 0.f;
}

static __device__ __forceinline__ void epi(float acc[2][8][4], float* __restrict__ out,
                                           int row0, int mbase, int nbase, int g, int t,
                                           const float* b0, const float* b1, const float* b2,
                                           int N, int doAdd) {
    float bias[8][2];
#pragma unroll
    for (int nf = 0; nf < 8; nf++) {
#pragma unroll
        for (int i = 0; i < 2; i++) {
            float bb = 0.f;
            int col = nbase + nf * 8 + t * 2 + i;
            if (b0) bb += __ldg(&b0[col]);
            if (b1) bb += __ldg(&b1[col]);
            if (b2) bb += __ldg(&b2[col]);
            bias[nf][i] = bb;
        }
    }
#pragma unroll
    for (int mf = 0; mf < 2; mf++) {
#pragma unroll
        for (int half = 0; half < 2; half++) {
            int row = row0 + mbase + mf * 16 + g + half * 8;
            if (row < N) {
                float* op = out + (size_t)row * 128 + nbase;
#pragma unroll
                for (int nf = 0; nf < 8; nf++) {
                    float x = acc[mf][nf][half * 2 + 0] + bias[nf][0];
                    float y = acc[mf][nf][half * 2 + 1] + bias[nf][1];
                    float2* p = (float2*)(op + nf * 8 + t * 2);
                    if (doAdd) {
                        float2 o = *p;
                        o.x += x; o.y += y;
                        *p = o;
                    } else {
                        *p = make_float2(x, y);
                    }
                }
            }
        }
    }
}

static __device__ __forceinline__ void epi_h16(float acc[2][8][4], __half* __restrict__ out,
                                               int row0, int mbase, int nbase, int g, int t,
                                               const float* b0, int N) {
    float bias[8][2];
#pragma unroll
    for (int nf = 0; nf < 8; nf++) {
#pragma unroll
        for (int i = 0; i < 2; i++)
            bias[nf][i] = __ldg(&b0[nbase + nf * 8 + t * 2 + i]);
    }
#pragma unroll
    for (int mf = 0; mf < 2; mf++) {
#pragma unroll
        for (int half = 0; half < 2; half++) {
            int row = row0 + mbase + mf * 16 + g + half * 8;
            if (row < N) {
                __half* op = out + (size_t)row * 128 + nbase;
#pragma unroll
                for (int nf = 0; nf < 8; nf++) {
                    float x = acc[mf][nf][half * 2 + 0] + bias[nf][0];
                    float y = acc[mf][nf][half * 2 + 1] + bias[nf][1];
                    *(__half2*)(op + nf * 8 + t * 2) = __floats2half2_rn(x, y);
                }
            }
        }
    }
}

// h = leaky(acc + br): store fp16 into A smem and fp16 to gmem (if hout)
static __device__ __forceinline__ void store_h(float acc[2][8][4], char* sm,
                                               const float* __restrict__ br_,
                                               __half* __restrict__ hout,
                                               int row0, int mbase, int nbase,
                                               int g, int t, int N) {
    float bias[8][2];
#pragma unroll
    for (int nf = 0; nf < 8; nf++) {
#pragma unroll
        for (int i = 0; i < 2; i++)
            bias[nf][i] = __ldg(&br_[nbase + nf * 8 + t * 2 + i]);
    }
#pragma unroll
    for (int mf = 0; mf < 2; mf++) {
#pragma unroll
        for (int half = 0; half < 2; half++) {
            int rl = mbase + mf * 16 + g + half * 8;
            int row = row0 + rl;
#pragma unroll
            for (int nf = 0; nf < 8; nf++) {
                float x = leakyf(acc[mf][nf][half * 2 + 0] + bias[nf][0]);
                float y = leakyf(acc[mf][nf][half * 2 + 1] + bias[nf][1]);
                int c = nbase + nf * 8 + t * 2;
                unsigned hv = pack_h2(x, y);
                *(unsigned*)(sm + A_OFF + rl * ROWB + c * 2) = hv;
                if (hout && row < N)
                    *(unsigned*)(hout + (size_t)row * 128 + c) = hv;
            }
        }
    }
}

// ---------------- kernel: hq=A@Wq+bq ; hk=A@Wk+bk ; [out=A@Wro+bro_sum] ----------------
// A source: fp32 (A32) when A16==null, else fp16 async copy
__global__ void __launch_bounds__(256, 2)
gemm_qk3(const float* __restrict__ A32, const __half* __restrict__ A16,
         int wq, int wk, int wo,
         const float* __restrict__ bq, const float* __restrict__ bk,
         const float* __restrict__ bro,
         __half* __restrict__ hq, __half* __restrict__ hk, float* __restrict__ out, int N) {
    extern __shared__ char sm[];
    uint32_t sbase = smem_u32(sm);
    int tid = threadIdx.x, w = tid >> 5, lane = tid & 31;
    int g = lane >> 2, t = lane & 3;
    int mbase = (w >> 1) * 32, nbase = (w & 1) * 64;
    int row0 = blockIdx.x * 128;

    copy_B_nc(sbase, B0_OFF, wq);
    if (A16) copy_A16_nc(sbase, A16, row0, N);
    cp_commit();                               // group1: B0 (+A16)
    if (!A16) conv_A(sm, A32, row0, N);
    copy_B_nc(sbase, B1_OFF, wk);
    cp_commit();                               // group2: B1

    cp_wait1();                                // group1 done
    __syncthreads();

    float acc[2][8][4];
    zero_acc(acc);
    run_mma(acc, sbase, B0_OFF, mbase, nbase, lane);
    epi_h16(acc, hq, row0, mbase, nbase, g, t, bq, N);

    cp_wait0();
    __syncthreads();
    if (wo >= 0) { copy_B_nc(sbase, B0_OFF, wo); cp_commit(); }

    zero_acc(acc);
    run_mma(acc, sbase, B1_OFF, mbase, nbase, lane);
    epi_h16(acc, hk, row0, mbase, nbase, g, t, bk, N);

    if (wo >= 0) {
        cp_wait0();
        __syncthreads();
        zero_acc(acc);
        run_mma(acc, sbase, B0_OFF, mbase, nbase, lane);
        epi(acc, out, row0, mbase, nbase, g, t, bro, bro + 128, bro + 256, N, 0);
    }
}

// ---------------- kernel: h = leaky(agg@Wr+br) [-> hout fp16]; out += h@Wro ----------------
__global__ void __launch_bounds__(256, 2)
gemm_wr_ro(const __half* __restrict__ agg, int wr, int wro,
           const float* __restrict__ br_, __half* __restrict__ hout,
           float* __restrict__ out, int N) {
    extern __shared__ char sm[];
    uint32_t sbase = smem_u32(sm);
    int tid = threadIdx.x, w = tid >> 5, lane = tid & 31;
    int g = lane >> 2, t = lane & 3;
    int mbase = (w >> 1) * 32, nbase = (w & 1) * 64;
    int row0 = blockIdx.x * 128;

    copy_B_nc(sbase, B0_OFF, wr);
    copy_A16_nc(sbase, agg, row0, N);
    cp_commit();                               // group1: B0 + A
    copy_B_nc(sbase, B1_OFF, wro);
    cp_commit();                               // group2: B1

    cp_wait1();
    __syncthreads();

    float acc[2][8][4];
    zero_acc(acc);
    run_mma(acc, sbase, B0_OFF, mbase, nbase, lane);

    __syncthreads();
    store_h(acc, sm, br_, hout, row0, mbase, nbase, g, t, N);
    cp_wait0();
    __syncthreads();

    zero_acc(acc);
    run_mma(acc, sbase, B1_OFF, mbase, nbase, lane);
    epi(acc, out, row0, mbase, nbase, g, t, nullptr, nullptr, nullptr, N, 1);
}

// ---------------- launch ----------------
extern "C" void kernel_launch(void* const* d_in, const int* in_sizes, int n_in,
                              void* d_out, int out_size) {
    const float* feats = (const float*)d_in[0];
    const float* Wq    = (const float*)d_in[1];
    const float* bq    = (const float*)d_in[2];
    const float* Wk    = (const float*)d_in[3];
    const float* bk    = (const float*)d_in[4];
    const float* Wr    = (const float*)d_in[5];
    const float* br    = (const float*)d_in[6];
    const float* Wro   = (const float*)d_in[7];
    const float* bro   = (const float*)d_in[8];
    const int*   src   = (const int*)d_in[9];
    const int*   dst   = (const int*)d_in[10];

    int N = in_sizes[0] / DIM;   // 50000
    int E = in_sizes[9];         // 800000
    float* out = (float*)d_out;

    __half *hq, *hk, *agg, *h1;
    int *cnt, *off, *cur, *csrc, *bsum;
    cudaGetSymbolAddress((void**)&hq,   g_hq);
    cudaGetSymbolAddress((void**)&hk,   g_hk);
    cudaGetSymbolAddress((void**)&agg,  g_agg);
    cudaGetSymbolAddress((void**)&h1,   g_h1);
    cudaGetSymbolAddress((void**)&cnt,  g_cnt);
    cudaGetSymbolAddress((void**)&off,  g_off);
    cudaGetSymbolAddress((void**)&cur,  g_cur);
    cudaGetSymbolAddress((void**)&csrc, g_csrc);
    cudaGetSymbolAddress((void**)&bsum, g_bsum);

    cudaFuncSetAttribute(gemm_qk3,   cudaFuncAttributeMaxDynamicSharedMemorySize, SMEM_TOTAL);
    cudaFuncSetAttribute(gemm_wr_ro, cudaFuncAttributeMaxDynamicSharedMemorySize, SMEM_TOTAL);

    int gM = (N + 127) / 128;    // 391
    int gAgg = (N * 32 + 255) / 256;
    int nb = (N + SCAN_BLK - 1) / SCAN_BLK;
    int e4 = (E + 3) / 4;

    // fork a second stream for the CSR build (independent of weights/GEMM-L0)
    cudaStream_t s2;
    cudaStreamCreateWithFlags(&s2, cudaStreamNonBlocking);
    cudaEvent_t evF, evJ;
    cudaEventCreateWithFlags(&evF, cudaEventDisableTiming);
    cudaEventCreateWithFlags(&evJ, cudaEventDisableTiming);

    cudaEventRecord(evF, 0);
    cudaStreamWaitEvent(s2, evF, 0);

    // ---- branch A (s2): CSR build ----
    zero_int<<<(N + 255) / 256, 256, 0, s2>>>(cnt, N);
    cnt_kernel<<<(e4 + 255) / 256, 256, 0, s2>>>(dst, E, cnt);
    scan_p1<<<nb, 256, 0, s2>>>(cnt, bsum, N);
    scan_p2<<<1, 32, 0, s2>>>(bsum, off, nb, N);
    scan_p3<<<nb, SCAN_BLK, 0, s2>>>(cnt, bsum, off, cur, N);
    scatter_kernel<<<(e4 + 255) / 256, 256, 0, s2>>>(src, dst, E, cur, csrc);
    cudaEventRecord(evJ, s2);

    // ---- branch B (stream 0): weights + layer-0 Q/K (+readout 0 folded) ----
    pack_w<<<9, 1024>>>(Wq, Wk, Wr, Wro);
    gemm_qk3<<<gM, 256, SMEM_TOTAL>>>(feats, nullptr, 0, 1, 6, bq, bk, bro,
                                      hq, hk, out, N);

    // join: agg needs both branches
    cudaStreamWaitEvent(0, evJ, 0);

    agg_csr<<<gAgg, 256>>>(off, csrc, hq, hk, agg, N);
    gemm_wr_ro<<<gM, 256, SMEM_TOTAL>>>(agg, 2, 7, br, h1, out, N);

    gemm_qk3<<<gM, 256, SMEM_TOTAL>>>(nullptr, h1, 3, 4, -1, bq + 128, bk + 128, nullptr,
                                      hq, hk, nullptr, N);
    agg_csr<<<gAgg, 256>>>(off, csrc, hq, hk, agg, N);
    gemm_wr_ro<<<gM, 256, SMEM_TOTAL>>>(agg, 5, 8, br + 128, nullptr, out, N);

    // NOTE: s2/events intentionally not destroyed (participated in capture;
    // host-side objects only, no device memory).
}

// round 17
// speedup vs baseline: 2.7625x; 1.0530x over previous
#include <cuda_runtime.h>
#include <cuda_fp16.h>
#include <cstdint>
#include <cstddef>

// ---------------- problem constants ----------------
#define N_NODES 50000
#define N_EDGES 800000
#define DIM     128
#define NEG_SLOPE 0.2f

// ---- SMEM: A (128 rows fp16) + two B buffers, 272B padded rows ----
#define ROWB      272
#define T_SZ      (128 * ROWB)          // 34816
#define A_OFF     0
#define B0_OFF    T_SZ
#define B1_OFF    (2 * T_SZ)
#define SMEM_TOTAL (3 * T_SZ)           // 104448

#define SCAN_BLK 1024
#define MAX_SB   64

// ---------------- scratch (device globals; no allocs allowed) ----------------
__device__ __half g_hq [(size_t)N_NODES * DIM];
__device__ __half g_hk [(size_t)N_NODES * DIM];
__device__ __half g_agg[(size_t)N_NODES * DIM];
__device__ unsigned g_wpack[9 * 8192];      // 9 x fp16 [n][k] images
__device__ int g_cnt[N_NODES];
__device__ int g_off[N_NODES + 1];
__device__ int g_cur[N_NODES];
__device__ int g_csrc[N_EDGES];
__device__ int g_bsum[MAX_SB];

__device__ __forceinline__ float leakyf(float x) { return x >= 0.f ? x : NEG_SLOPE * x; }

static __device__ __forceinline__ unsigned pack_h2(float a, float b) {
    __half2 h = __floats2half2_rn(a, b);
    return *(unsigned*)&h;
}
static __device__ __forceinline__ uint32_t smem_u32(const void* p) {
    uint32_t a;
    asm("{ .reg .u64 t; cvta.to.shared.u64 t, %1; cvt.u32.u64 %0, t; }" : "=r"(a) : "l"(p));
    return a;
}
static __device__ __forceinline__ void cp16(uint32_t d, const void* s) {
    asm volatile("cp.async.cg.shared.global [%0], [%1], 16;" :: "r"(d), "l"(s));
}
static __device__ __forceinline__ void cp_commit() {
    asm volatile("cp.async.commit_group;");
}
static __device__ __forceinline__ void cp_wait0() {
    asm volatile("cp.async.wait_group 0;");
}
static __device__ __forceinline__ void cp_wait1() {
    asm volatile("cp.async.wait_group 1;");
}

// ---------------- CSR build ----------------
__global__ void zero_int(int* __restrict__ p, int n) {
    int i = blockIdx.x * blockDim.x + threadIdx.x;
    if (i < n) p[i] = 0;
}
__global__ void cnt_kernel(const int* __restrict__ dst, int E, int* __restrict__ cnt) {
    int i4 = blockIdx.x * blockDim.x + threadIdx.x;
    int base = i4 * 4;
    if (base + 3 < E) {
        int4 d = __ldg((const int4*)(dst + base));
        atomicAdd(&cnt[d.x], 1);
        atomicAdd(&cnt[d.y], 1);
        atomicAdd(&cnt[d.z], 1);
        atomicAdd(&cnt[d.w], 1);
    } else {
        for (int j = base; j < E; j++) atomicAdd(&cnt[__ldg(&dst[j])], 1);
    }
}
__global__ void scan_p1(const int* __restrict__ cnt, int* __restrict__ bsum, int n) {
    __shared__ int wsh[8];
    int tid = threadIdx.x;
    int base = blockIdx.x * SCAN_BLK;
    int s = 0;
#pragma unroll
    for (int j = 0; j < 4; j++) {
        int i = base + j * 256 + tid;
        if (i < n) s += __ldg(&cnt[i]);
    }
#pragma unroll
    for (int d = 16; d > 0; d >>= 1) s += __shfl_down_sync(0xffffffffu, s, d);
    if ((tid & 31) == 0) wsh[tid >> 5] = s;
    __syncthreads();
    if (tid < 8) {
        int v = wsh[tid];
#pragma unroll
        for (int d = 4; d > 0; d >>= 1) v += __shfl_down_sync(0xffu, v, d);
        if (tid == 0) bsum[blockIdx.x] = v;
    }
}
__global__ void scan_p2(int* __restrict__ bsum, int* __restrict__ off, int nb, int n) {
    int lane = threadIdx.x;
    int v0 = (lane < nb)      ? bsum[lane]      : 0;
    int v1 = (32 + lane < nb) ? bsum[32 + lane] : 0;
    int s0 = v0, s1 = v1;
#pragma unroll
    for (int d = 1; d < 32; d <<= 1) {
        int t0 = __shfl_up_sync(0xffffffffu, s0, d);
        int t1 = __shfl_up_sync(0xffffffffu, s1, d);
        if (lane >= d) { s0 += t0; s1 += t1; }
    }
    int tot0 = __shfl_sync(0xffffffffu, s0, 31);
    int tot1 = __shfl_sync(0xffffffffu, s1, 31);
    if (lane < nb)      bsum[lane]      = s0 - v0;
    if (32 + lane < nb) bsum[32 + lane] = tot0 + s1 - v1;
    if (lane == 0) off[n] = tot0 + tot1;
}
__global__ void scan_p3(const int* __restrict__ cnt, const int* __restrict__ bsum,
                        int* __restrict__ off, int* __restrict__ cur, int n) {
    __shared__ int wsh[32];
    int tid = threadIdx.x;
    int lane = tid & 31, w = tid >> 5;
    int i = blockIdx.x * SCAN_BLK + tid;
    int v = (i < n) ? __ldg(&cnt[i]) : 0;
    int s = v;
#pragma unroll
    for (int d = 1; d < 32; d <<= 1) {
        int t = __shfl_up_sync(0xffffffffu, s, d);
        if (lane >= d) s += t;
    }
    if (lane == 31) wsh[w] = s;
    __syncthreads();
    if (w == 0) {
        int x = wsh[lane];
#pragma unroll
        for (int d = 1; d < 32; d <<= 1) {
            int t = __shfl_up_sync(0xffffffffu, x, d);
            if (lane >= d) x += t;
        }
        wsh[lane] = x;
    }
    __syncthreads();
    int excl = s - v + (w ? wsh[w - 1] : 0) + __ldg(&bsum[blockIdx.x]);
    if (i < n) { off[i] = excl; cur[i] = excl; }
}
__global__ void scatter_kernel(const int* __restrict__ src, const int* __restrict__ dst,
                               int E, int* __restrict__ cur, int* __restrict__ csrc) {
    int i4 = blockIdx.x * blockDim.x + threadIdx.x;
    int base = i4 * 4;
    if (base + 3 < E) {
        int4 d = __ldg((const int4*)(dst + base));
        int4 s = __ldg((const int4*)(src + base));
        csrc[atomicAdd(&cur[d.x], 1)] = s.x;
        csrc[atomicAdd(&cur[d.y], 1)] = s.y;
        csrc[atomicAdd(&cur[d.z], 1)] = s.z;
        csrc[atomicAdd(&cur[d.w], 1)] = s.w;
    } else {
        for (int j = base; j < E; j++) {
            int pos = atomicAdd(&cur[__ldg(&dst[j])], 1);
            csrc[pos] = __ldg(&src[j]);
        }
    }
}

// ---------------- CSR aggregation: warp per dst node, fp16 in/out ----------------
__global__ void agg_csr(const int* __restrict__ off, const int* __restrict__ csrc,
                        const __half* __restrict__ hq, const __half* __restrict__ hk,
                        __half* __restrict__ agg, int N) {
    int warp = (blockIdx.x * blockDim.x + threadIdx.x) >> 5;
    int lane = threadIdx.x & 31;
    if (warp >= N) return;
    int b = __ldg(&off[warp]);
    int e = __ldg(&off[warp + 1]);
    uint2 qraw = __ldg(((const uint2*)hq) + (size_t)warp * 32 + lane);
    float2 q01 = __half22float2(*(const __half2*)&qraw.x);
    float2 q23 = __half22float2(*(const __half2*)&qraw.y);
    float4 q = make_float4(q01.x, q01.y, q23.x, q23.y);
    float4 acc = make_float4(0.f, 0.f, 0.f, 0.f);
    for (int base = b; base < e; base += 32) {
        int s = (base + lane < e) ? __ldg(&csrc[base + lane]) : 0;
        int m = min(32, e - base);
        for (int j = 0; j < m; j++) {
            int sj = __shfl_sync(0xffffffffu, s, j);
            uint2 kraw = __ldg(((const uint2*)hk) + (size_t)sj * 32 + lane);
            float2 k01 = __half22float2(*(const __half2*)&kraw.x);
            float2 k23 = __half22float2(*(const __half2*)&kraw.y);
            acc.x += leakyf(q.x + k01.x);
            acc.y += leakyf(q.y + k01.y);
            acc.z += leakyf(q.z + k23.x);
            acc.w += leakyf(q.w + k23.y);
        }
    }
    float inv = 1.f / (float)max(e - b, 1);
    uint2 o;
    o.x = pack_h2(acc.x * inv, acc.y * inv);
    o.y = pack_h2(acc.z * inv, acc.w * inv);
    ((uint2*)agg)[(size_t)warp * 32 + lane] = o;
}

// ---------------- pack weights: fp16 images, layout [n][k] ----------------
__global__ void pack_w(const float* __restrict__ Wq, const float* __restrict__ Wk,
                       const float* __restrict__ Wr, const float* __restrict__ Wro) {
    int mat = blockIdx.x;  // 0..8
    const float* W;
    switch (mat) {
        case 0: W = Wq;         break;
        case 1: W = Wk;         break;
        case 2: W = Wr;         break;
        case 3: W = Wq + 16384; break;
        case 4: W = Wk + 16384; break;
        case 5: W = Wr + 16384; break;
        default: W = Wro + (mat - 6) * 16384; break;
    }
    unsigned short* img = (unsigned short*)(g_wpack + (size_t)mat * 8192);
    int n  = threadIdx.x & 127;
    int kc = threadIdx.x >> 7;
#pragma unroll
    for (int j = 0; j < 16; j++) {
        int k = kc * 16 + j;
        float w = __ldg(&W[k * 128 + n]);
        __half h = __float2half_rn(w);
        img[n * 128 + k] = *(unsigned short*)&h;
    }
}

// ---------------- GEMM building blocks (256 threads/CTA, 128-row fp16 tiles) ----------------
static __device__ __forceinline__ void conv_A(char* sm, const float* __restrict__ A,
                                              int row0, int N) {
#pragma unroll
    for (int it = 0; it < 16; it++) {
        int idx = it * 256 + threadIdx.x;
        int r  = idx >> 5;
        int c4 = idx & 31;
        int gidx = row0 + r;
        int gc = gidx < N ? gidx : N - 1;
        float4 v = __ldg(((const float4*)(A + (size_t)gc * 128)) + c4);
        *(uint2*)(sm + A_OFF + r * ROWB + c4 * 8) =
            make_uint2(pack_h2(v.x, v.y), pack_h2(v.z, v.w));
    }
}

static __device__ __forceinline__ void copy_A16_nc(uint32_t sbase, const __half* __restrict__ A,
                                                   int row0, int N) {
#pragma unroll
    for (int it = 0; it < 8; it++) {
        int i = it * 256 + threadIdx.x;
        int r = i >> 4, c = i & 15;
        int gidx = row0 + r;
        int gc = gidx < N ? gidx : N - 1;
        cp16(sbase + A_OFF + r * ROWB + c * 16, A + (size_t)gc * 128 + c * 8);
    }
}

static __device__ __forceinline__ void copy_B_nc(uint32_t sbase, int bufOff, int widx) {
    const char* src = (const char*)(g_wpack + (size_t)widx * 8192);
    uint32_t dst = sbase + bufOff;
#pragma unroll
    for (int it = 0; it < 8; it++) {
        int i = it * 256 + threadIdx.x;
        int r = i >> 4, c = i & 15;
        cp16(dst + r * ROWB + c * 16, src + i * 16);
    }
}

static __device__ __forceinline__ void mma_f16(float* c, const uint32_t* a,
                                               uint32_t b0, uint32_t b1) {
    asm volatile("mma.sync.aligned.m16n8k16.row.col.f32.f16.f16.f32 "
                 "{%0,%1,%2,%3}, {%4,%5,%6,%7}, {%8,%9}, {%0,%1,%2,%3};"
                 : "+f"(c[0]), "+f"(c[1]), "+f"(c[2]), "+f"(c[3])
                 : "r"(a[0]), "r"(a[1]), "r"(a[2]), "r"(a[3]), "r"(b0), "r"(b1));
}
static __device__ __forceinline__ void ldsm_x4(uint32_t* r, uint32_t addr) {
    asm volatile("ldmatrix.sync.aligned.m8n8.x4.shared.b16 {%0,%1,%2,%3}, [%4];"
                 : "=r"(r[0]), "=r"(r[1]), "=r"(r[2]), "=r"(r[3]) : "r"(addr));
}

static __device__ __forceinline__ void run_mma(float acc[2][8][4], uint32_t sbase,
                                               int bufOff, int mbase, int nbase, int lane) {
    uint32_t aoff = (uint32_t)((mbase + (lane & 15)) * ROWB + (lane >> 4) * 16);
    uint32_t brow = (uint32_t)(nbase + (lane & 7) + ((lane >> 4) << 3));
    uint32_t boff = brow * ROWB + ((lane >> 3) & 1) * 16;
    uint32_t Aa = sbase + A_OFF + aoff;
    uint32_t Ba = sbase + bufOff + boff;
#pragma unroll
    for (int ks = 0; ks < 8; ks++) {
        uint32_t kb = ks * 32;
        uint32_t a0[4], a1[4];
        ldsm_x4(a0, Aa + kb);
        ldsm_x4(a1, Aa + 16 * ROWB + kb);
#pragma unroll
        for (int p = 0; p < 4; p++) {
            uint32_t b[4];
            ldsm_x4(b, Ba + p * (16 * ROWB) + kb);
            int nf0 = 2 * p, nf1 = 2 * p + 1;
            mma_f16(acc[0][nf0], a0, b[0], b[1]);
            mma_f16(acc[1][nf0], a1, b[0], b[1]);
            mma_f16(acc[0][nf1], a0, b[2], b[3]);
            mma_f16(acc[1][nf1], a1, b[2], b[3]);
        }
    }
}

static __device__ __forceinline__ void zero_acc(float acc[2][8][4]) {
#pragma unroll
    for (int mf = 0; mf < 2; mf++)
#pragma unroll
        for (int nf = 0; nf < 8; nf++)
#pragma unroll
            for (int i = 0; i < 4; i++) acc[mf][nf][i] = 0.f;
}

static __device__ __forceinline__ void epi(float acc[2][8][4], float* __restrict__ out,
                                           int row0, int mbase, int nbase, int g, int t,
                                           const float* b0, const float* b1, const float* b2,
                                           int N, int doAdd) {
    float bias[8][2];
#pragma unroll
    for (int nf = 0; nf < 8; nf++) {
#pragma unroll
        for (int i = 0; i < 2; i++) {
            float bb = 0.f;
            int col = nbase + nf * 8 + t * 2 + i;
            if (b0) bb += __ldg(&b0[col]);
            if (b1) bb += __ldg(&b1[col]);
            if (b2) bb += __ldg(&b2[col]);
            bias[nf][i] = bb;
        }
    }
#pragma unroll
    for (int mf = 0; mf < 2; mf++) {
#pragma unroll
        for (int half = 0; half < 2; half++) {
            int row = row0 + mbase + mf * 16 + g + half * 8;
            if (row < N) {
                float* op = out + (size_t)row * 128 + nbase;
#pragma unroll
                for (int nf = 0; nf < 8; nf++) {
                    float x = acc[mf][nf][half * 2 + 0] + bias[nf][0];
                    float y = acc[mf][nf][half * 2 + 1] + bias[nf][1];
                    float2* p = (float2*)(op + nf * 8 + t * 2);
                    if (doAdd) {
                        float2 o = *p;
                        o.x += x; o.y += y;
                        *p = o;
                    } else {
                        *p = make_float2(x, y);
                    }
                }
            }
        }
    }
}

static __device__ __forceinline__ void epi_h16(float acc[2][8][4], __half* __restrict__ out,
                                               int row0, int mbase, int nbase, int g, int t,
                                               const float* b0, int N) {
    float bias[8][2];
#pragma unroll
    for (int nf = 0; nf < 8; nf++) {
#pragma unroll
        for (int i = 0; i < 2; i++)
            bias[nf][i] = __ldg(&b0[nbase + nf * 8 + t * 2 + i]);
    }
#pragma unroll
    for (int mf = 0; mf < 2; mf++) {
#pragma unroll
        for (int half = 0; half < 2; half++) {
            int row = row0 + mbase + mf * 16 + g + half * 8;
            if (row < N) {
                __half* op = out + (size_t)row * 128 + nbase;
#pragma unroll
                for (int nf = 0; nf < 8; nf++) {
                    float x = acc[mf][nf][half * 2 + 0] + bias[nf][0];
                    float y = acc[mf][nf][half * 2 + 1] + bias[nf][1];
                    *(__half2*)(op + nf * 8 + t * 2) = __floats2half2_rn(x, y);
                }
            }
        }
    }
}

// h = leaky(acc + br): store fp16 into A smem only
static __device__ __forceinline__ void store_h_sm(float acc[2][8][4], char* sm,
                                                  const float* __restrict__ br_,
                                                  int mbase, int nbase, int g, int t) {
    float bias[8][2];
#pragma unroll
    for (int nf = 0; nf < 8; nf++) {
#pragma unroll
        for (int i = 0; i < 2; i++)
            bias[nf][i] = __ldg(&br_[nbase + nf * 8 + t * 2 + i]);
    }
#pragma unroll
    for (int mf = 0; mf < 2; mf++) {
#pragma unroll
        for (int half = 0; half < 2; half++) {
            int rl = mbase + mf * 16 + g + half * 8;
#pragma unroll
            for (int nf = 0; nf < 8; nf++) {
                float x = leakyf(acc[mf][nf][half * 2 + 0] + bias[nf][0]);
                float y = leakyf(acc[mf][nf][half * 2 + 1] + bias[nf][1]);
                int c = nbase + nf * 8 + t * 2;
                *(unsigned*)(sm + A_OFF + rl * ROWB + c * 2) = pack_h2(x, y);
            }
        }
    }
}

// ---------------- kernel: hq=A@Wq+bq ; hk=A@Wk+bk ; out=A@Wro+bro_sum ----------------
__global__ void __launch_bounds__(256, 2)
gemm_qk3(const float* __restrict__ A32, int wq, int wk, int wo,
         const float* __restrict__ bq, const float* __restrict__ bk,
         const float* __restrict__ bro,
         __half* __restrict__ hq, __half* __restrict__ hk, float* __restrict__ out, int N) {
    extern __shared__ char sm[];
    uint32_t sbase = smem_u32(sm);
    int tid = threadIdx.x, w = tid >> 5, lane = tid & 31;
    int g = lane >> 2, t = lane & 3;
    int mbase = (w >> 1) * 32, nbase = (w & 1) * 64;
    int row0 = blockIdx.x * 128;

    copy_B_nc(sbase, B0_OFF, wq);
    cp_commit();                               // G1: B0
    conv_A(sm, A32, row0, N);
    copy_B_nc(sbase, B1_OFF, wk);
    cp_commit();                               // G2: B1

    cp_wait1();
    __syncthreads();

    float acc[2][8][4];
    zero_acc(acc);
    run_mma(acc, sbase, B0_OFF, mbase, nbase, lane);
    epi_h16(acc, hq, row0, mbase, nbase, g, t, bq, N);

    cp_wait0();
    __syncthreads();
    copy_B_nc(sbase, B0_OFF, wo);
    cp_commit();                               // G3: B0 (Wro)

    zero_acc(acc);
    run_mma(acc, sbase, B1_OFF, mbase, nbase, lane);
    epi_h16(acc, hk, row0, mbase, nbase, g, t, bk, N);

    cp_wait0();
    __syncthreads();
    zero_acc(acc);
    run_mma(acc, sbase, B0_OFF, mbase, nbase, lane);
    epi(acc, out, row0, mbase, nbase, g, t, bro, bro + 128, bro + 256, N, 0);
}

// ---------------- MEGA kernel (layer-0 tail + layer-1 head, h1 never in gmem):
// h = leaky(agg@Wr + br); out += h@Wro; hq = h@Wq + bq; hk = h@Wk + bk
__global__ void __launch_bounds__(256, 2)
gemm_mega(const __half* __restrict__ agg, int wr, int wro, int wq, int wk,
          const float* __restrict__ br_, const float* __restrict__ bq,
          const float* __restrict__ bk,
          __half* __restrict__ hq, __half* __restrict__ hk,
          float* __restrict__ out, int N) {
    extern __shared__ char sm[];
    uint32_t sbase = smem_u32(sm);
    int tid = threadIdx.x, w = tid >> 5, lane = tid & 31;
    int g = lane >> 2, t = lane & 3;
    int mbase = (w >> 1) * 32, nbase = (w & 1) * 64;
    int row0 = blockIdx.x * 128;

    copy_B_nc(sbase, B0_OFF, wr);
    copy_A16_nc(sbase, agg, row0, N);
    cp_commit();                               // G1: B0 + A
    copy_B_nc(sbase, B1_OFF, wro);
    cp_commit();                               // G2: B1 (Wro)

    cp_wait1();                                // G1 done
    __syncthreads();

    float acc[2][8][4];
    // stage 1: Wr
    zero_acc(acc);
    run_mma(acc, sbase, B0_OFF, mbase, nbase, lane);
    __syncthreads();                           // all warps done reading A + B0
    store_h_sm(acc, sm, br_, mbase, nbase, g, t);   // A := h (fp16)
    copy_B_nc(sbase, B0_OFF, wq);
    cp_commit();                               // G3: B0 (Wq)

    cp_wait1();                                // G2 done (B1=Wro ready)
    __syncthreads();                           // h visible

    // stage 2: Wro -> out +=
    zero_acc(acc);
    run_mma(acc, sbase, B1_OFF, mbase, nbase, lane);
    epi(acc, out, row0, mbase, nbase, g, t, nullptr, nullptr, nullptr, N, 1);
    __syncthreads();                           // all done reading B1
    copy_B_nc(sbase, B1_OFF, wk);
    cp_commit();                               // G4: B1 (Wk)

    cp_wait1();                                // G3 done (B0=Wq ready)
    __syncthreads();

    // stage 3: Wq -> hq
    zero_acc(acc);
    run_mma(acc, sbase, B0_OFF, mbase, nbase, lane);
    epi_h16(acc, hq, row0, mbase, nbase, g, t, bq, N);

    cp_wait0();                                // G4 done (B1=Wk ready)
    __syncthreads();

    // stage 4: Wk -> hk
    zero_acc(acc);
    run_mma(acc, sbase, B1_OFF, mbase, nbase, lane);
    epi_h16(acc, hk, row0, mbase, nbase, g, t, bk, N);
}

// ---------------- kernel: h = leaky(agg@Wr+br) (smem only); out += h@Wro ----------------
__global__ void __launch_bounds__(256, 2)
gemm_wr_ro(const __half* __restrict__ agg, int wr, int wro,
           const float* __restrict__ br_, float* __restrict__ out, int N) {
    extern __shared__ char sm[];
    uint32_t sbase = smem_u32(sm);
    int tid = threadIdx.x, w = tid >> 5, lane = tid & 31;
    int g = lane >> 2, t = lane & 3;
    int mbase = (w >> 1) * 32, nbase = (w & 1) * 64;
    int row0 = blockIdx.x * 128;

    copy_B_nc(sbase, B0_OFF, wr);
    copy_A16_nc(sbase, agg, row0, N);
    cp_commit();                               // G1
    copy_B_nc(sbase, B1_OFF, wro);
    cp_commit();                               // G2

    cp_wait1();
    __syncthreads();

    float acc[2][8][4];
    zero_acc(acc);
    run_mma(acc, sbase, B0_OFF, mbase, nbase, lane);

    __syncthreads();
    store_h_sm(acc, sm, br_, mbase, nbase, g, t);
    cp_wait0();
    __syncthreads();

    zero_acc(acc);
    run_mma(acc, sbase, B1_OFF, mbase, nbase, lane);
    epi(acc, out, row0, mbase, nbase, g, t, nullptr, nullptr, nullptr, N, 1);
}

// ---------------- launch ----------------
extern "C" void kernel_launch(void* const* d_in, const int* in_sizes, int n_in,
                              void* d_out, int out_size) {
    const float* feats = (const float*)d_in[0];
    const float* Wq    = (const float*)d_in[1];
    const float* bq    = (const float*)d_in[2];
    const float* Wk    = (const float*)d_in[3];
    const float* bk    = (const float*)d_in[4];
    const float* Wr    = (const float*)d_in[5];
    const float* br    = (const float*)d_in[6];
    const float* Wro   = (const float*)d_in[7];
    const float* bro   = (const float*)d_in[8];
    const int*   src   = (const int*)d_in[9];
    const int*   dst   = (const int*)d_in[10];

    int N = in_sizes[0] / DIM;   // 50000
    int E = in_sizes[9];         // 800000
    float* out = (float*)d_out;

    __half *hq, *hk, *agg;
    int *cnt, *off, *cur, *csrc, *bsum;
    cudaGetSymbolAddress((void**)&hq,   g_hq);
    cudaGetSymbolAddress((void**)&hk,   g_hk);
    cudaGetSymbolAddress((void**)&agg,  g_agg);
    cudaGetSymbolAddress((void**)&cnt,  g_cnt);
    cudaGetSymbolAddress((void**)&off,  g_off);
    cudaGetSymbolAddress((void**)&cur,  g_cur);
    cudaGetSymbolAddress((void**)&csrc, g_csrc);
    cudaGetSymbolAddress((void**)&bsum, g_bsum);

    cudaFuncSetAttribute(gemm_qk3,   cudaFuncAttributeMaxDynamicSharedMemorySize, SMEM_TOTAL);
    cudaFuncSetAttribute(gemm_mega,  cudaFuncAttributeMaxDynamicSharedMemorySize, SMEM_TOTAL);
    cudaFuncSetAttribute(gemm_wr_ro, cudaFuncAttributeMaxDynamicSharedMemorySize, SMEM_TOTAL);

    int gM = (N + 127) / 128;    // 391
    int gAgg = (N * 32 + 255) / 256;
    int nb = (N + SCAN_BLK - 1) / SCAN_BLK;
    int e4 = (E + 3) / 4;

    cudaStream_t s2;
    cudaStreamCreateWithFlags(&s2, cudaStreamNonBlocking);
    cudaEvent_t evF, evJ;
    cudaEventCreateWithFlags(&evF, cudaEventDisableTiming);
    cudaEventCreateWithFlags(&evJ, cudaEventDisableTiming);

    cudaEventRecord(evF, 0);
    cudaStreamWaitEvent(s2, evF, 0);

    // ---- branch A (s2): CSR build ----
    zero_int<<<(N + 255) / 256, 256, 0, s2>>>(cnt, N);
    cnt_kernel<<<(e4 + 255) / 256, 256, 0, s2>>>(dst, E, cnt);
    scan_p1<<<nb, 256, 0, s2>>>(cnt, bsum, N);
    scan_p2<<<1, 32, 0, s2>>>(bsum, off, nb, N);
    scan_p3<<<nb, SCAN_BLK, 0, s2>>>(cnt, bsum, off, cur, N);
    scatter_kernel<<<(e4 + 255) / 256, 256, 0, s2>>>(src, dst, E, cur, csrc);
    cudaEventRecord(evJ, s2);

    // ---- branch B (stream 0): weights + layer-0 Q/K/readout0 ----
    pack_w<<<9, 1024>>>(Wq, Wk, Wr, Wro);
    gemm_qk3<<<gM, 256, SMEM_TOTAL>>>(feats, 0, 1, 6, bq, bk, bro, hq, hk, out, N);

    // join: agg needs CSR
    cudaStreamWaitEvent(0, evJ, 0);

    agg_csr<<<gAgg, 256>>>(off, csrc, hq, hk, agg, N);
    // layer-0 tail + layer-1 head fused: h1 stays in smem
    gemm_mega<<<gM, 256, SMEM_TOTAL>>>(agg, 2, 7, 3, 4, br, bq + 128, bk + 128,
                                       hq, hk, out, N);
    agg_csr<<<gAgg, 256>>>(off, csrc, hq, hk, agg, N);
    gemm_wr_ro<<<gM, 256, SMEM_TOTAL>>>(agg, 5, 8, br + 128, out, N);

    // NOTE: s2/events intentionally not destroyed (participated in capture;
    // host-side objects only, no device memory).
}